// round 1
// baseline (speedup 1.0000x reference)
#include <cuda_runtime.h>
#include <math.h>

// ---------------- problem constants ----------------
constexpr int B_  = 4;
constexpr int T_  = 2048;
constexpr int E_  = 1024;
constexpr int H_  = 16;
constexpr int HD_ = 64;     // head dim
constexpr int LQ_ = 2;      // quantum layers
constexpr int M_  = B_ * T_;        // 8192 rows
constexpr int NTOT_ = M_ * H_;      // 131072 quantum elements

// ---------------- scratch (device globals; no allocs allowed) ----------------
__device__ float g_q[(size_t)M_ * E_];
__device__ float g_k[(size_t)M_ * E_];
__device__ float g_v[(size_t)M_ * E_];
__device__ float g_s[(size_t)B_ * T_ * T_];
__device__ float g_attn[(size_t)M_ * E_];
__device__ float g_zc[(size_t)M_ * 64];
__device__ float g_wosub[(size_t)E_ * 64];
__device__ float g_base[H_ * 16];

// ---------------- generic tiled fp32 GEMM ----------------
// NT: C[m,n] = alpha * sum_k A[m,k] * B[n,k]   (A: MxK row-major, B: NxK row-major)
// NN: C[m,n] = alpha * sum_k A[m,k] * B[k,n]   (B: KxN row-major, ld = N)
// Batched via blockIdx.z with element strides sA/sB/sC.
// Requires M%128==0, N%128==0, K%16==0.
template <bool NT>
__global__ __launch_bounds__(256) void gemm_kernel(
    const float* __restrict__ A, const float* __restrict__ B, float* __restrict__ C,
    int M, int N, int K, size_t sA, size_t sB, size_t sC, float alpha)
{
    constexpr int BM = 128, BN = 128, BK = 16;
    __shared__ float As[BK][BM];
    __shared__ float Bs[BK][BN];

    const int tid = threadIdx.x;
    const int tx  = tid & 15;   // 0..15  -> 8 cols each
    const int ty  = tid >> 4;   // 0..15  -> 8 rows each
    const int row0 = blockIdx.y * BM;
    const int col0 = blockIdx.x * BN;

    A += (size_t)blockIdx.z * sA + (size_t)row0 * K;
    C += (size_t)blockIdx.z * sC;
    if (NT) B += (size_t)blockIdx.z * sB + (size_t)col0 * K;
    else    B += (size_t)blockIdx.z * sB + col0;

    float acc[8][8];
#pragma unroll
    for (int i = 0; i < 8; i++)
#pragma unroll
        for (int j = 0; j < 8; j++) acc[i][j] = 0.f;

    const int lrow = tid >> 2;          // 0..63  (K-major tile loads)
    const int lcol = (tid & 3) << 2;    // 0,4,8,12
    const int nrow = tid >> 5;          // 0..7   (N-major tile loads, NN)
    const int ncol = (tid & 31) << 2;   // 0..124

    for (int k0 = 0; k0 < K; k0 += BK) {
        // A tile (always K-major source), stored transposed As[k][m]
#pragma unroll
        for (int r = 0; r < 2; r++) {
            float4 va = *(const float4*)(A + (size_t)(lrow + r * 64) * K + (k0 + lcol));
            As[lcol + 0][lrow + r * 64] = va.x;
            As[lcol + 1][lrow + r * 64] = va.y;
            As[lcol + 2][lrow + r * 64] = va.z;
            As[lcol + 3][lrow + r * 64] = va.w;
        }
        if (NT) {
#pragma unroll
            for (int r = 0; r < 2; r++) {
                float4 vb = *(const float4*)(B + (size_t)(lrow + r * 64) * K + (k0 + lcol));
                Bs[lcol + 0][lrow + r * 64] = vb.x;
                Bs[lcol + 1][lrow + r * 64] = vb.y;
                Bs[lcol + 2][lrow + r * 64] = vb.z;
                Bs[lcol + 3][lrow + r * 64] = vb.w;
            }
        } else {
#pragma unroll
            for (int r = 0; r < 2; r++) {
                float4 vb = *(const float4*)(B + (size_t)(k0 + nrow + r * 8) * N + ncol);
                *(float4*)&Bs[nrow + r * 8][ncol] = vb;
            }
        }
        __syncthreads();

#pragma unroll
        for (int kk = 0; kk < BK; kk++) {
            float a[8], b[8];
            *(float4*)&a[0] = *(const float4*)&As[kk][ty * 8];
            *(float4*)&a[4] = *(const float4*)&As[kk][ty * 8 + 4];
            *(float4*)&b[0] = *(const float4*)&Bs[kk][tx * 8];
            *(float4*)&b[4] = *(const float4*)&Bs[kk][tx * 8 + 4];
#pragma unroll
            for (int i = 0; i < 8; i++)
#pragma unroll
                for (int j = 0; j < 8; j++)
                    acc[i][j] = fmaf(a[i], b[j], acc[i][j]);
        }
        __syncthreads();
    }

#pragma unroll
    for (int i = 0; i < 8; i++) {
        size_t crow = (size_t)(row0 + ty * 8 + i) * N + col0 + tx * 8;
#pragma unroll
        for (int j = 0; j < 8; j += 4) {
            float4 o;
            o.x = acc[i][j + 0] * alpha;
            o.y = acc[i][j + 1] * alpha;
            o.z = acc[i][j + 2] * alpha;
            o.w = acc[i][j + 3] * alpha;
            *(float4*)(C + crow + j) = o;
        }
    }
}

// ---------------- row softmax over 2048 cols, values held in registers ----------------
__global__ __launch_bounds__(256) void softmax_kernel(float* __restrict__ S)
{
    constexpr int C = T_, TPB = 256, PER = C / TPB;  // 8
    float* row = S + (size_t)blockIdx.x * C;
    const int t = threadIdx.x;

    float v[PER];
    float m = -1e30f;
#pragma unroll
    for (int j = 0; j < PER; j++) {
        v[j] = row[t + j * TPB];
        m = fmaxf(m, v[j]);
    }
    __shared__ float red[TPB];
    red[t] = m;
    __syncthreads();
#pragma unroll
    for (int s = TPB / 2; s > 0; s >>= 1) {
        if (t < s) red[t] = fmaxf(red[t], red[t + s]);
        __syncthreads();
    }
    m = red[0];
    __syncthreads();

    float sum = 0.f;
#pragma unroll
    for (int j = 0; j < PER; j++) {
        v[j] = expf(v[j] - m);
        sum += v[j];
    }
    red[t] = sum;
    __syncthreads();
#pragma unroll
    for (int s = TPB / 2; s > 0; s >>= 1) {
        if (t < s) red[t] += red[t + s];
        __syncthreads();
    }
    float inv = 1.f / red[0];
#pragma unroll
    for (int j = 0; j < PER; j++)
        row[t + j * TPB] = v[j] * inv;
}

// ---------------- quantum circuit pieces ----------------
// state index i over 4 qubits; qubit q owns bit (8 >> q) (axis 1+q of (N,2,2,2,2)).
template <int BIT>
__device__ __forceinline__ void apply_ry_bit(float st[16], float half_theta)
{
    float s, c;
    sincosf(half_theta, &s, &c);
#pragma unroll
    for (int i = 0; i < 16; i++) {
        if (!(i & BIT)) {
            float a0 = st[i], a1 = st[i | BIT];
            st[i]       = c * a0 - s * a1;
            st[i | BIT] = s * a0 + c * a1;
        }
    }
}

template <int BC, int BT>
__device__ __forceinline__ void apply_cnot(float st[16])
{
#pragma unroll
    for (int i = 0; i < 16; i++) {
        if ((i & BC) && !(i & BT)) {
            float tmp = st[i];
            st[i] = st[i | BT];
            st[i | BT] = tmp;
        }
    }
}

// Variational layers depend only on head h -> 16 base states, computed once.
__global__ void base_kernel(const float* __restrict__ qparams, float* __restrict__ base)
{
    int h = threadIdx.x;
    if (h >= H_) return;
    float st[16];
#pragma unroll
    for (int i = 0; i < 16; i++) st[i] = 0.f;
    st[0] = 1.f;
#pragma unroll
    for (int l = 0; l < LQ_; l++) {
        const float* p = qparams + (h * LQ_ + l) * 4;
        apply_ry_bit<8>(st, 0.5f * p[0]);
        apply_ry_bit<4>(st, 0.5f * p[1]);
        apply_ry_bit<2>(st, 0.5f * p[2]);
        apply_ry_bit<1>(st, 0.5f * p[3]);
        apply_cnot<8, 4>(st);  // (0,1)
        apply_cnot<4, 2>(st);  // (1,2)
        apply_cnot<2, 1>(st);  // (2,3)
        apply_cnot<1, 8>(st);  // (3,0)
    }
#pragma unroll
    for (int i = 0; i < 16; i++) base[h * 16 + i] = st[i];
}

// Per (b,t,h): 4 encoding RYs on the head's base state, then Z expectations.
__global__ __launch_bounds__(256) void quantum_kernel(
    const float* __restrict__ attn, const float* __restrict__ base, float* __restrict__ zc)
{
    int idx = blockIdx.x * 256 + threadIdx.x;
    if (idx >= NTOT_) return;
    int bt = idx >> 4;
    int h  = idx & 15;

    float st[16];
#pragma unroll
    for (int i = 0; i < 16; i++) st[i] = base[h * 16 + i];

    const float* xin = attn + (size_t)bt * E_ + h * HD_;
    apply_ry_bit<8>(st, 0.5f * xin[0]);
    apply_ry_bit<4>(st, 0.5f * xin[1]);
    apply_ry_bit<2>(st, 0.5f * xin[2]);
    apply_ry_bit<1>(st, 0.5f * xin[3]);

    float z0 = 0.f, z1 = 0.f, z2 = 0.f, z3 = 0.f;
#pragma unroll
    for (int i = 0; i < 16; i++) {
        float p = st[i] * st[i];
        z0 += (i & 8) ? -p : p;
        z1 += (i & 4) ? -p : p;
        z2 += (i & 2) ? -p : p;
        z3 += (i & 1) ? -p : p;
    }
    size_t o = (size_t)bt * 64 + h * 4;
    zc[o + 0] = z0;
    zc[o + 1] = z1;
    zc[o + 2] = z2;
    zc[o + 3] = z3;
}

// Gather the 64 useful columns of Wo: WoSub[e][j] = Wo[e, (j>>2)*64 + (j&3)]
__global__ void wosub_kernel(const float* __restrict__ Wo, float* __restrict__ ws)
{
    int idx = blockIdx.x * 256 + threadIdx.x;  // E_*64 = 65536
    int e = idx >> 6, j = idx & 63;
    ws[idx] = Wo[(size_t)e * E_ + ((j >> 2) << 6) + (j & 3)];
}

// ---------------- launch ----------------
extern "C" void kernel_launch(void* const* d_in, const int* in_sizes, int n_in,
                              void* d_out, int out_size)
{
    (void)in_sizes; (void)n_in; (void)out_size;
    const float* x  = (const float*)d_in[0];
    const float* Wq = (const float*)d_in[1];
    const float* Wk = (const float*)d_in[2];
    const float* Wv = (const float*)d_in[3];
    const float* Wo = (const float*)d_in[4];
    const float* qp = (const float*)d_in[5];
    float* out = (float*)d_out;

    float *pq, *pk, *pv, *ps, *pa, *pz, *pw, *pb;
    cudaGetSymbolAddress((void**)&pq, g_q);
    cudaGetSymbolAddress((void**)&pk, g_k);
    cudaGetSymbolAddress((void**)&pv, g_v);
    cudaGetSymbolAddress((void**)&ps, g_s);
    cudaGetSymbolAddress((void**)&pa, g_attn);
    cudaGetSymbolAddress((void**)&pz, g_zc);
    cudaGetSymbolAddress((void**)&pw, g_wosub);
    cudaGetSymbolAddress((void**)&pb, g_base);

    // tiny precomputations
    base_kernel<<<1, 32>>>(qp, pb);
    wosub_kernel<<<(E_ * 64) / 256, 256>>>(Wo, pw);

    // Q, K, V projections: (8192x1024) x (1024x1024)^T
    dim3 gproj(E_ / 128, M_ / 128);
    gemm_kernel<true><<<gproj, 256>>>(x, Wq, pq, M_, E_, E_, 0, 0, 0, 1.f);
    gemm_kernel<true><<<gproj, 256>>>(x, Wk, pk, M_, E_, E_, 0, 0, 0, 1.f);
    gemm_kernel<true><<<gproj, 256>>>(x, Wv, pv, M_, E_, E_, 0, 0, 0, 1.f);

    // scores = Q K^T / sqrt(E), batched over B
    dim3 gsc(T_ / 128, T_ / 128, B_);
    gemm_kernel<true><<<gsc, 256>>>(pq, pk, ps, T_, T_, E_,
                                    (size_t)T_ * E_, (size_t)T_ * E_, (size_t)T_ * T_,
                                    1.f / 32.f);

    // softmax over last axis (8192 rows of 2048)
    softmax_kernel<<<M_, 256>>>(ps);

    // out = softmax(scores) @ V, batched
    dim3 gout(E_ / 128, T_ / 128, B_);
    gemm_kernel<false><<<gout, 256>>>(ps, pv, pa, T_, E_, T_,
                                      (size_t)T_ * T_, (size_t)T_ * E_, (size_t)T_ * E_,
                                      1.f);

    // quantum readout -> compact (8192 x 64)
    quantum_kernel<<<NTOT_ / 256, 256>>>(pa, pb, pz);

    // final projection: (8192 x 64) x (1024 x 64)^T -> d_out
    dim3 gfin(E_ / 128, M_ / 128);
    gemm_kernel<true><<<gfin, 256>>>(pz, pw, out, M_, E_, 64, 0, 0, 0, 1.f);
}

// round 3
// speedup vs baseline: 2.1591x; 2.1591x over previous
#include <cuda_runtime.h>
#include <cuda_bf16.h>
#include <math.h>
#include <stdint.h>

// ---------------- problem constants ----------------
constexpr int B_  = 4;
constexpr int T_  = 2048;
constexpr int E_  = 1024;
constexpr int H_  = 16;
constexpr int LQ_ = 2;
constexpr int M_  = B_ * T_;        // 8192
constexpr int NTOT_ = M_ * H_;      // 131072

// ---------------- scratch (device globals; no allocs allowed) ----------------
__device__ __nv_bfloat16 g_xh[(size_t)M_ * E_],  g_xl[(size_t)M_ * E_];
__device__ __nv_bfloat16 g_wqh[(size_t)E_ * E_], g_wql[(size_t)E_ * E_];
__device__ __nv_bfloat16 g_wkh[(size_t)E_ * E_], g_wkl[(size_t)E_ * E_];
__device__ __nv_bfloat16 g_wvh[(size_t)E_ * E_], g_wvl[(size_t)E_ * E_];
__device__ __nv_bfloat16 g_qh[(size_t)M_ * E_],  g_ql[(size_t)M_ * E_];
__device__ __nv_bfloat16 g_kh[(size_t)M_ * E_],  g_kl[(size_t)M_ * E_];
__device__ __nv_bfloat16 g_vth[(size_t)E_ * M_], g_vtl[(size_t)E_ * M_];   // V^T [E][M]
__device__ float         g_s[(size_t)B_ * T_ * T_];
__device__ __nv_bfloat16 g_sh[(size_t)B_ * T_ * T_], g_sl[(size_t)B_ * T_ * T_];
__device__ float         g_attn[(size_t)M_ * E_];
__device__ __nv_bfloat16 g_zch[(size_t)M_ * 64], g_zcl[(size_t)M_ * 64];
__device__ __nv_bfloat16 g_wsh[(size_t)E_ * 64], g_wsl[(size_t)E_ * 64];
__device__ float         g_base[H_ * 16];

// ---------------- helpers ----------------
__device__ __forceinline__ uint32_t smem_u32(const void* p) {
    uint32_t a;
    asm("{ .reg .u64 t; cvta.to.shared.u64 t, %1; cvt.u32.u64 %0, t; }" : "=r"(a) : "l"(p));
    return a;
}
#define CP16(dst, src) asm volatile("cp.async.cg.shared.global [%0], [%1], 16;" :: "r"(dst), "l"(src))
#define CPCOMMIT()     asm volatile("cp.async.commit_group;")
#define CPWAIT1()      asm volatile("cp.async.wait_group 1;")

__device__ __forceinline__ void ldmx4(uint32_t* r, uint32_t addr) {
    asm volatile("ldmatrix.sync.aligned.m8n8.x4.shared.b16 {%0,%1,%2,%3}, [%4];"
                 : "=r"(r[0]), "=r"(r[1]), "=r"(r[2]), "=r"(r[3]) : "r"(addr));
}
__device__ __forceinline__ void mma16816(float* c, const uint32_t* a, const uint32_t* b) {
    asm volatile(
        "mma.sync.aligned.m16n8k16.row.col.f32.bf16.bf16.f32 "
        "{%0,%1,%2,%3}, {%4,%5,%6,%7}, {%8,%9}, {%0,%1,%2,%3};"
        : "+f"(c[0]), "+f"(c[1]), "+f"(c[2]), "+f"(c[3])
        : "r"(a[0]), "r"(a[1]), "r"(a[2]), "r"(a[3]), "r"(b[0]), "r"(b[1]));
}

// pack two fp32 into bf16x2 (low half = first arg)
__device__ __forceinline__ uint32_t pack_bf16(float lo, float hi) {
    uint32_t u;
    asm("cvt.rn.bf16x2.f32 %0, %1, %2;" : "=r"(u) : "f"(hi), "f"(lo));
    return u;
}
__device__ __forceinline__ float bflo(uint32_t u) { return __uint_as_float(u << 16); }
__device__ __forceinline__ float bfhi(uint32_t u) { return __uint_as_float(u & 0xFFFF0000u); }

// ---------------- bf16 3-pass NT GEMM (mma.sync) ----------------
// C[m,n] = alpha * sum_k A[m,k]*B[n,k], where A ~= Ah+Al, B ~= Bh+Bl (bf16 planes).
// C = Ah*Bh + Ah*Bl + Al*Bh  accumulated in fp32.
// M,N from grid (128x128 tiles); K%32==0. Batched via blockIdx.z strides.
// Outputs: optional fp32 Cf, optional bf16 hi/lo planes Ch/Cl.
constexpr int LDSB = 80;                    // padded smem row: 40 bf16 = 80 bytes
constexpr int PLANE = 128 * LDSB;           // 10240 B
constexpr int STAGE = 4 * PLANE;            // 40960 B
constexpr int NSTG  = 3;
constexpr int SMEM_GEMM = NSTG * STAGE;     // 122880 B

__global__ __launch_bounds__(256, 1) void gemm_bf3(
    const __nv_bfloat16* __restrict__ Ah, const __nv_bfloat16* __restrict__ Al,
    const __nv_bfloat16* __restrict__ Bh, const __nv_bfloat16* __restrict__ Bl,
    float* __restrict__ Cf, __nv_bfloat16* __restrict__ Ch, __nv_bfloat16* __restrict__ Cl,
    int K, int lda, int ldb, int ldc,
    size_t sA, size_t sB, size_t sC, float alpha)
{
    extern __shared__ char smem[];
    const uint32_t sb = smem_u32(smem);
    const int tid = threadIdx.x;
    const int lane = tid & 31;
    const int warp = tid >> 5;
    const int row0 = blockIdx.y * 128;
    const int col0 = blockIdx.x * 128;

    Ah += (size_t)blockIdx.z * sA; Al += (size_t)blockIdx.z * sA;
    Bh += (size_t)blockIdx.z * sB; Bl += (size_t)blockIdx.z * sB;

    // per-thread cp.async source setup: 2 chunks (16B) per plane
    const int ldrow = tid >> 1;                  // 0..127
    const int kc0   = (tid & 1) * 2;             // 0 or 2 (16B chunks)
    const __nv_bfloat16* gp[4] = {
        Ah + (size_t)(row0 + ldrow) * lda + kc0 * 8,
        Al + (size_t)(row0 + ldrow) * lda + kc0 * 8,
        Bh + (size_t)(col0 + ldrow) * ldb + kc0 * 8,
        Bl + (size_t)(col0 + ldrow) * ldb + kc0 * 8 };
    const uint32_t sdst0 = sb + (uint32_t)(ldrow * LDSB + kc0 * 16);

    const int ntiles = K >> 5;

    auto load_tile = [&](int kt, int slot) {
        const uint32_t base = sdst0 + (uint32_t)slot * STAGE;
#pragma unroll
        for (int p = 0; p < 4; p++) {
            const __nv_bfloat16* src = gp[p] + (size_t)kt * 32;
            const uint32_t dst = base + (uint32_t)p * PLANE;
            CP16(dst,      src);
            CP16(dst + 16, src + 8);
        }
    };

    load_tile(0, 0); CPCOMMIT();
    load_tile(1, 1); CPCOMMIT();

    const int wm = (warp & 1) * 64;      // warp M offset
    const int wn = (warp >> 1) * 32;     // warp N offset

    float acc[4][4][4];
#pragma unroll
    for (int i = 0; i < 4; i++)
#pragma unroll
        for (int j = 0; j < 4; j++)
#pragma unroll
            for (int r = 0; r < 4; r++) acc[i][j][r] = 0.f;

    // precomputed intra-tile ldmatrix offsets
    const uint32_t a_off = (uint32_t)((wm + (lane & 15)) * LDSB + ((lane >> 4) * 8) * 2);
    const int nrow = (lane & 7) + ((lane >> 4) * 8);
    const uint32_t b_off = (uint32_t)((wn + nrow) * LDSB + (((lane >> 3) & 1) * 8) * 2);

    for (int i = 0; i < ntiles; i++) {
        CPWAIT1();
        __syncthreads();
        if (i + 2 < ntiles) load_tile(i + 2, (i + 2) % NSTG);
        CPCOMMIT();

        const uint32_t st = sb + (uint32_t)(i % NSTG) * STAGE;
#pragma unroll
        for (int kk = 0; kk < 2; kk++) {
            uint32_t ah[4][4], al_[4][4], bh[4][2], bl_[4][2];
#pragma unroll
            for (int im = 0; im < 4; im++) {
                uint32_t ao = st + a_off + (uint32_t)(im * 16 * LDSB + kk * 32);
                ldmx4(ah[im],  ao);
                ldmx4(al_[im], ao + PLANE);
            }
#pragma unroll
            for (int jb = 0; jb < 2; jb++) {
                uint32_t bo = st + 2 * PLANE + b_off + (uint32_t)(jb * 16 * LDSB + kk * 32);
                uint32_t r[4];
                ldmx4(r, bo);
                bh[jb * 2][0] = r[0]; bh[jb * 2][1] = r[1];
                bh[jb * 2 + 1][0] = r[2]; bh[jb * 2 + 1][1] = r[3];
                ldmx4(r, bo + PLANE);
                bl_[jb * 2][0] = r[0]; bl_[jb * 2][1] = r[1];
                bl_[jb * 2 + 1][0] = r[2]; bl_[jb * 2 + 1][1] = r[3];
            }
#pragma unroll
            for (int im = 0; im < 4; im++)
#pragma unroll
                for (int jn = 0; jn < 4; jn++) {
                    mma16816(acc[im][jn], ah[im],  bh[jn]);
                    mma16816(acc[im][jn], ah[im],  bl_[jn]);
                    mma16816(acc[im][jn], al_[im], bh[jn]);
                }
        }
        __syncthreads();
    }

    // ---- epilogue: frags -> smem fp32 -> global ----
    float* se = (float*)smem;                       // [128][132]
    const int er = wm + (lane >> 2);
    const int ec = wn + (lane & 3) * 2;
#pragma unroll
    for (int im = 0; im < 4; im++)
#pragma unroll
        for (int jn = 0; jn < 4; jn++) {
            float* p0 = se + (size_t)(er + im * 16) * 132 + ec + jn * 8;
            p0[0]   = acc[im][jn][0];
            p0[1]   = acc[im][jn][1];
            p0[132 * 8]     = acc[im][jn][2];
            p0[132 * 8 + 1] = acc[im][jn][3];
        }
    __syncthreads();

    {
        const int row = tid >> 1;
        const int hc  = (tid & 1) * 64;
        const size_t crow = (size_t)blockIdx.z * sC + (size_t)(row0 + row) * ldc + col0 + hc;
#pragma unroll
        for (int j = 0; j < 16; j++) {
            float4 v = *(const float4*)(se + (size_t)row * 132 + hc + j * 4);
            v.x *= alpha; v.y *= alpha; v.z *= alpha; v.w *= alpha;
            if (Cf) *(float4*)(Cf + crow + j * 4) = v;
            if (Ch) {
                uint32_t h0 = pack_bf16(v.x, v.y);
                uint32_t h1 = pack_bf16(v.z, v.w);
                *(uint2*)(Ch + crow + j * 4) = make_uint2(h0, h1);
                uint32_t l0 = pack_bf16(v.x - bflo(h0), v.y - bfhi(h0));
                uint32_t l1 = pack_bf16(v.z - bflo(h1), v.w - bfhi(h1));
                *(uint2*)(Cl + crow + j * 4) = make_uint2(l0, l1);
            }
        }
    }
}

// ---------------- fp32 -> bf16 hi/lo planes ----------------
__global__ __launch_bounds__(256) void conv_kernel(
    const float* __restrict__ src, __nv_bfloat16* __restrict__ h, __nv_bfloat16* __restrict__ l)
{
    size_t i = ((size_t)blockIdx.x * 256 + threadIdx.x) * 4;
    float4 v = *(const float4*)(src + i);
    uint32_t h0 = pack_bf16(v.x, v.y);
    uint32_t h1 = pack_bf16(v.z, v.w);
    *(uint2*)(h + i) = make_uint2(h0, h1);
    uint32_t l0 = pack_bf16(v.x - bflo(h0), v.y - bfhi(h0));
    uint32_t l1 = pack_bf16(v.z - bflo(h1), v.w - bfhi(h1));
    *(uint2*)(l + i) = make_uint2(l0, l1);
}

// ---------------- row softmax over 2048 cols -> bf16 hi/lo ----------------
__global__ __launch_bounds__(256) void softmax_kernel(
    const float* __restrict__ S, __nv_bfloat16* __restrict__ Wh, __nv_bfloat16* __restrict__ Wl)
{
    constexpr int C = T_, TPB = 256, PER = C / TPB;
    const float* row = S + (size_t)blockIdx.x * C;
    const int t = threadIdx.x;

    float v[PER];
    float m = -1e30f;
#pragma unroll
    for (int j = 0; j < PER; j++) { v[j] = row[t + j * TPB]; m = fmaxf(m, v[j]); }
    __shared__ float red[TPB];
    red[t] = m;
    __syncthreads();
#pragma unroll
    for (int s = TPB / 2; s > 0; s >>= 1) {
        if (t < s) red[t] = fmaxf(red[t], red[t + s]);
        __syncthreads();
    }
    m = red[0];
    __syncthreads();
    float sum = 0.f;
#pragma unroll
    for (int j = 0; j < PER; j++) { v[j] = expf(v[j] - m); sum += v[j]; }
    red[t] = sum;
    __syncthreads();
#pragma unroll
    for (int s = TPB / 2; s > 0; s >>= 1) {
        if (t < s) red[t] += red[t + s];
        __syncthreads();
    }
    float inv = 1.f / red[0];
    size_t base = (size_t)blockIdx.x * C;
#pragma unroll
    for (int j = 0; j < PER; j++) {
        float w = v[j] * inv;
        __nv_bfloat16 h = __float2bfloat16(w);
        Wh[base + t + j * TPB] = h;
        Wl[base + t + j * TPB] = __float2bfloat16(w - __bfloat162float(h));
    }
}

// ---------------- quantum circuit ----------------
template <int BIT>
__device__ __forceinline__ void apply_ry_bit(float st[16], float half_theta)
{
    float s, c;
    sincosf(half_theta, &s, &c);
#pragma unroll
    for (int i = 0; i < 16; i++) {
        if (!(i & BIT)) {
            float a0 = st[i], a1 = st[i | BIT];
            st[i]       = c * a0 - s * a1;
            st[i | BIT] = s * a0 + c * a1;
        }
    }
}
template <int BC, int BT>
__device__ __forceinline__ void apply_cnot(float st[16])
{
#pragma unroll
    for (int i = 0; i < 16; i++) {
        if ((i & BC) && !(i & BT)) {
            float tmp = st[i]; st[i] = st[i | BT]; st[i | BT] = tmp;
        }
    }
}

__global__ void base_kernel(const float* __restrict__ qparams, float* __restrict__ base)
{
    int h = threadIdx.x;
    if (h >= H_) return;
    float st[16];
#pragma unroll
    for (int i = 0; i < 16; i++) st[i] = 0.f;
    st[0] = 1.f;
#pragma unroll
    for (int l = 0; l < LQ_; l++) {
        const float* p = qparams + (h * LQ_ + l) * 4;
        apply_ry_bit<8>(st, 0.5f * p[0]);
        apply_ry_bit<4>(st, 0.5f * p[1]);
        apply_ry_bit<2>(st, 0.5f * p[2]);
        apply_ry_bit<1>(st, 0.5f * p[3]);
        apply_cnot<8, 4>(st);
        apply_cnot<4, 2>(st);
        apply_cnot<2, 1>(st);
        apply_cnot<1, 8>(st);
    }
#pragma unroll
    for (int i = 0; i < 16; i++) base[h * 16 + i] = st[i];
}

__global__ __launch_bounds__(256) void quantum_kernel(
    const float* __restrict__ attn, const float* __restrict__ base,
    __nv_bfloat16* __restrict__ zh, __nv_bfloat16* __restrict__ zl)
{
    int idx = blockIdx.x * 256 + threadIdx.x;
    if (idx >= NTOT_) return;
    int bt = idx >> 4;
    int h  = idx & 15;

    float st[16];
#pragma unroll
    for (int i = 0; i < 16; i++) st[i] = base[h * 16 + i];

    const float* xin = attn + (size_t)bt * E_ + h * 64;
    apply_ry_bit<8>(st, 0.5f * xin[0]);
    apply_ry_bit<4>(st, 0.5f * xin[1]);
    apply_ry_bit<2>(st, 0.5f * xin[2]);
    apply_ry_bit<1>(st, 0.5f * xin[3]);

    float z[4] = {0.f, 0.f, 0.f, 0.f};
#pragma unroll
    for (int i = 0; i < 16; i++) {
        float p = st[i] * st[i];
        z[0] += (i & 8) ? -p : p;
        z[1] += (i & 4) ? -p : p;
        z[2] += (i & 2) ? -p : p;
        z[3] += (i & 1) ? -p : p;
    }
    size_t o = (size_t)bt * 64 + h * 4;
#pragma unroll
    for (int q = 0; q < 4; q++) {
        __nv_bfloat16 hh = __float2bfloat16(z[q]);
        zh[o + q] = hh;
        zl[o + q] = __float2bfloat16(z[q] - __bfloat162float(hh));
    }
}

// Gather the 64 useful columns of Wo into hi/lo planes
__global__ void wosub_kernel(const float* __restrict__ Wo,
                             __nv_bfloat16* __restrict__ wh, __nv_bfloat16* __restrict__ wl)
{
    int idx = blockIdx.x * 256 + threadIdx.x;   // E_*64
    int e = idx >> 6, j = idx & 63;
    float v = Wo[(size_t)e * E_ + ((j >> 2) << 6) + (j & 3)];
    __nv_bfloat16 h = __float2bfloat16(v);
    wh[idx] = h;
    wl[idx] = __float2bfloat16(v - __bfloat162float(h));
}

// ---------------- launch ----------------
extern "C" void kernel_launch(void* const* d_in, const int* in_sizes, int n_in,
                              void* d_out, int out_size)
{
    (void)in_sizes; (void)n_in; (void)out_size;
    const float* x  = (const float*)d_in[0];
    const float* Wq = (const float*)d_in[1];
    const float* Wk = (const float*)d_in[2];
    const float* Wv = (const float*)d_in[3];
    const float* Wo = (const float*)d_in[4];
    const float* qp = (const float*)d_in[5];
    float* out = (float*)d_out;

    __nv_bfloat16 *xh, *xl, *wqh, *wql, *wkh, *wkl, *wvh, *wvl;
    __nv_bfloat16 *qh, *ql, *kh, *kl, *vth, *vtl, *sh, *sl, *zch, *zcl, *wsh, *wsl;
    float *ps, *pa, *pb;
    cudaGetSymbolAddress((void**)&xh,  g_xh);  cudaGetSymbolAddress((void**)&xl,  g_xl);
    cudaGetSymbolAddress((void**)&wqh, g_wqh); cudaGetSymbolAddress((void**)&wql, g_wql);
    cudaGetSymbolAddress((void**)&wkh, g_wkh); cudaGetSymbolAddress((void**)&wkl, g_wkl);
    cudaGetSymbolAddress((void**)&wvh, g_wvh); cudaGetSymbolAddress((void**)&wvl, g_wvl);
    cudaGetSymbolAddress((void**)&qh,  g_qh);  cudaGetSymbolAddress((void**)&ql,  g_ql);
    cudaGetSymbolAddress((void**)&kh,  g_kh);  cudaGetSymbolAddress((void**)&kl,  g_kl);
    cudaGetSymbolAddress((void**)&vth, g_vth); cudaGetSymbolAddress((void**)&vtl, g_vtl);
    cudaGetSymbolAddress((void**)&sh,  g_sh);  cudaGetSymbolAddress((void**)&sl,  g_sl);
    cudaGetSymbolAddress((void**)&zch, g_zch); cudaGetSymbolAddress((void**)&zcl, g_zcl);
    cudaGetSymbolAddress((void**)&wsh, g_wsh); cudaGetSymbolAddress((void**)&wsl, g_wsl);
    cudaGetSymbolAddress((void**)&ps,  g_s);
    cudaGetSymbolAddress((void**)&pa,  g_attn);
    cudaGetSymbolAddress((void**)&pb,  g_base);

    cudaFuncSetAttribute(gemm_bf3, cudaFuncAttributeMaxDynamicSharedMemorySize, SMEM_GEMM);

    // conversions + tiny precomputations
    conv_kernel<<<(M_ * E_) / 1024, 256>>>(x,  xh,  xl);
    conv_kernel<<<(E_ * E_) / 1024, 256>>>(Wq, wqh, wql);
    conv_kernel<<<(E_ * E_) / 1024, 256>>>(Wk, wkh, wkl);
    conv_kernel<<<(E_ * E_) / 1024, 256>>>(Wv, wvh, wvl);
    base_kernel<<<1, 32>>>(qp, pb);
    wosub_kernel<<<(E_ * 64) / 256, 256>>>(Wo, wsh, wsl);

    // Q = x Wq^T, K = x Wk^T : out bf16 planes only
    {
        dim3 g(E_ / 128, M_ / 128);
        gemm_bf3<<<g, 256, SMEM_GEMM>>>(xh, xl, wqh, wql, nullptr, qh, ql,
                                        E_, E_, E_, E_, 0, 0, 0, 1.f);
        gemm_bf3<<<g, 256, SMEM_GEMM>>>(xh, xl, wkh, wkl, nullptr, kh, kl,
                                        E_, E_, E_, E_, 0, 0, 0, 1.f);
    }
    // V^T = Wv x^T : [E][M] bf16 planes
    {
        dim3 g(M_ / 128, E_ / 128);
        gemm_bf3<<<g, 256, SMEM_GEMM>>>(wvh, wvl, xh, xl, nullptr, vth, vtl,
                                        E_, E_, E_, M_, 0, 0, 0, 1.f);
    }
    // scores = Q K^T / 32 (fp32), batched over B
    {
        dim3 g(T_ / 128, T_ / 128, B_);
        gemm_bf3<<<g, 256, SMEM_GEMM>>>(qh, ql, kh, kl, ps, nullptr, nullptr,
                                        E_, E_, E_, T_,
                                        (size_t)T_ * E_, (size_t)T_ * E_, (size_t)T_ * T_,
                                        1.f / 32.f);
    }
    softmax_kernel<<<M_, 256>>>(ps, sh, sl);
    // attn = w @ V  (A = w planes, B = Vt rows), fp32 out
    {
        dim3 g(E_ / 128, T_ / 128, B_);
        gemm_bf3<<<g, 256, SMEM_GEMM>>>(sh, sl, vth, vtl, pa, nullptr, nullptr,
                                        T_, T_, M_, E_,
                                        (size_t)T_ * T_, (size_t)T_, (size_t)T_ * E_,
                                        1.f);
    }
    quantum_kernel<<<NTOT_ / 256, 256>>>(pa, pb, zch, zcl);
    // out = zc @ WoSub^T (K=64), fp32 out
    {
        dim3 g(E_ / 128, M_ / 128);
        gemm_bf3<<<g, 256, SMEM_GEMM>>>(zch, zcl, wsh, wsl, out, nullptr, nullptr,
                                        64, 64, 64, E_, 0, 0, 0, 1.f);
    }
}

// round 4
// speedup vs baseline: 5.1495x; 2.3850x over previous
#include <cuda_runtime.h>
#include <cuda_fp16.h>
#include <math.h>
#include <stdint.h>

// ---------------- problem constants ----------------
constexpr int B_  = 4;
constexpr int T_  = 2048;
constexpr int E_  = 1024;
constexpr int H_  = 16;
constexpr int LQ_ = 2;
constexpr int M_  = B_ * T_;        // 8192
constexpr int NTOT_ = M_ * H_;      // 131072

// ---------------- scratch (device globals; no allocs allowed) ----------------
__device__ __half g_xh[(size_t)M_ * E_];
__device__ __half g_wqh[(size_t)E_ * E_];
__device__ __half g_wkh[(size_t)E_ * E_];
__device__ __half g_wvh[(size_t)E_ * E_];
__device__ __half g_qh[(size_t)M_ * E_];
__device__ __half g_kh[(size_t)M_ * E_];
__device__ __half g_vth[(size_t)E_ * M_];          // V^T [E][M]
__device__ float  g_s[(size_t)B_ * T_ * T_];
__device__ __half g_sh[(size_t)B_ * T_ * T_];
__device__ float  g_attn[(size_t)M_ * E_];
__device__ float  g_zc[(size_t)M_ * 64];
__device__ float  g_wosub[(size_t)E_ * 64];
__device__ float  g_base[H_ * 16];

// ---------------- helpers ----------------
__device__ __forceinline__ uint32_t smem_u32(const void* p) {
    uint32_t a;
    asm("{ .reg .u64 t; cvta.to.shared.u64 t, %1; cvt.u32.u64 %0, t; }" : "=r"(a) : "l"(p));
    return a;
}
#define CP16(dst, src) asm volatile("cp.async.cg.shared.global [%0], [%1], 16;" :: "r"(dst), "l"(src))
#define CPCOMMIT()     asm volatile("cp.async.commit_group;")
#define CPWAIT2()      asm volatile("cp.async.wait_group 2;")

__device__ __forceinline__ void ldmx4(uint32_t* r, uint32_t addr) {
    asm volatile("ldmatrix.sync.aligned.m8n8.x4.shared.b16 {%0,%1,%2,%3}, [%4];"
                 : "=r"(r[0]), "=r"(r[1]), "=r"(r[2]), "=r"(r[3]) : "r"(addr));
}
__device__ __forceinline__ void mma16816(float* c, const uint32_t* a, const uint32_t* b) {
    asm volatile(
        "mma.sync.aligned.m16n8k16.row.col.f32.f16.f16.f32 "
        "{%0,%1,%2,%3}, {%4,%5,%6,%7}, {%8,%9}, {%0,%1,%2,%3};"
        : "+f"(c[0]), "+f"(c[1]), "+f"(c[2]), "+f"(c[3])
        : "r"(a[0]), "r"(a[1]), "r"(a[2]), "r"(a[3]), "r"(b[0]), "r"(b[1]));
}
// pack two fp32 into f16x2 (first arg = low half; matches bf16 convention validated R3)
__device__ __forceinline__ uint32_t pack_f16(float lo, float hi) {
    uint32_t u;
    asm("cvt.rn.f16x2.f32 %0, %1, %2;" : "=r"(u) : "f"(hi), "f"(lo));
    return u;
}

// ---------------- fp16 single-pass NT GEMM (mma.sync) ----------------
// C[m,n] = alpha * sum_k A[m,k]*B[n,k]; fp32 accumulate.
// 128x128 CTA tile, BK=32, 4-stage cp.async pipeline, 8 warps (64x32 each).
constexpr int LDSB  = 80;                  // padded row: 32 halves = 64B data + 16B pad
constexpr int PLANE = 128 * LDSB;          // 10240 B
constexpr int STAGE = 2 * PLANE;           // 20480 B (A + B)
constexpr int NSTG  = 4;
constexpr int SMEM_GEMM = 128 * 132 * 4;   // 67584 (epilogue) < NSTG*STAGE=81920
constexpr int SMEM_DYN  = NSTG * STAGE;    // 81920

__global__ __launch_bounds__(256, 2) void gemm_h(
    const __half* __restrict__ Ah, const __half* __restrict__ Bh,
    float* __restrict__ Cf, __half* __restrict__ Ch,
    int K, int lda, int ldb, int ldc,
    size_t sA, size_t sB, size_t sC, float alpha)
{
    extern __shared__ char smem[];
    const uint32_t sb = smem_u32(smem);
    const int tid = threadIdx.x;
    const int lane = tid & 31;
    const int warp = tid >> 5;
    const int row0 = blockIdx.y * 128;
    const int col0 = blockIdx.x * 128;

    Ah += (size_t)blockIdx.z * sA;
    Bh += (size_t)blockIdx.z * sB;

    const int ldrow = tid >> 1;                  // 0..127
    const int kc0   = (tid & 1) * 2;             // 16B-chunk index 0 or 2
    const __half* gpA = Ah + (size_t)(row0 + ldrow) * lda + kc0 * 8;
    const __half* gpB = Bh + (size_t)(col0 + ldrow) * ldb + kc0 * 8;
    const uint32_t sdst0 = sb + (uint32_t)(ldrow * LDSB + kc0 * 16);

    const int ntiles = K >> 5;

    auto load_tile = [&](int kt, int slot) {
        const uint32_t base = sdst0 + (uint32_t)slot * STAGE;
        const __half* sa = gpA + (size_t)kt * 32;
        const __half* sbp = gpB + (size_t)kt * 32;
        CP16(base,              sa);
        CP16(base + 16,         sa + 8);
        CP16(base + PLANE,      sbp);
        CP16(base + PLANE + 16, sbp + 8);
    };

    load_tile(0, 0); CPCOMMIT();
    load_tile(1, 1); CPCOMMIT();
    load_tile(2, 2); CPCOMMIT();

    const int wm = (warp & 1) * 64;
    const int wn = (warp >> 1) * 32;

    float acc[4][4][4];
#pragma unroll
    for (int i = 0; i < 4; i++)
#pragma unroll
        for (int j = 0; j < 4; j++)
#pragma unroll
            for (int r = 0; r < 4; r++) acc[i][j][r] = 0.f;

    const uint32_t a_off = (uint32_t)((wm + (lane & 15)) * LDSB + ((lane >> 4) * 8) * 2);
    const int nrow = (lane & 7) + ((lane >> 4) * 8);
    const uint32_t b_off = (uint32_t)((wn + nrow) * LDSB + (((lane >> 3) & 1) * 8) * 2);

    for (int i = 0; i < ntiles; i++) {
        CPWAIT2();
        __syncthreads();
        if (i + 3 < ntiles) load_tile(i + 3, (i + 3) % NSTG);
        CPCOMMIT();

        const uint32_t st = sb + (uint32_t)(i % NSTG) * STAGE;
#pragma unroll
        for (int kk = 0; kk < 2; kk++) {
            uint32_t ah[4][4], bh[4][2];
#pragma unroll
            for (int im = 0; im < 4; im++)
                ldmx4(ah[im], st + a_off + (uint32_t)(im * 16 * LDSB + kk * 32));
#pragma unroll
            for (int jb = 0; jb < 2; jb++) {
                uint32_t r[4];
                ldmx4(r, st + PLANE + b_off + (uint32_t)(jb * 16 * LDSB + kk * 32));
                bh[jb * 2][0] = r[0];     bh[jb * 2][1] = r[1];
                bh[jb * 2 + 1][0] = r[2]; bh[jb * 2 + 1][1] = r[3];
            }
#pragma unroll
            for (int im = 0; im < 4; im++)
#pragma unroll
                for (int jn = 0; jn < 4; jn++)
                    mma16816(acc[im][jn], ah[im], bh[jn]);
        }
        __syncthreads();
    }

    // ---- epilogue: frags -> smem fp32 -> global ----
    float* se = (float*)smem;                        // [128][132]
    const int er = wm + (lane >> 2);
    const int ec = wn + (lane & 3) * 2;
#pragma unroll
    for (int im = 0; im < 4; im++)
#pragma unroll
        for (int jn = 0; jn < 4; jn++) {
            float* p0 = se + (size_t)(er + im * 16) * 132 + ec + jn * 8;
            p0[0] = acc[im][jn][0];
            p0[1] = acc[im][jn][1];
            p0[132 * 8]     = acc[im][jn][2];
            p0[132 * 8 + 1] = acc[im][jn][3];
        }
    __syncthreads();
    {
        const int row = tid >> 1;
        const int hc  = (tid & 1) * 64;
        const size_t crow = (size_t)blockIdx.z * sC + (size_t)(row0 + row) * ldc + col0 + hc;
#pragma unroll
        for (int j = 0; j < 16; j++) {
            float4 v = *(const float4*)(se + (size_t)row * 132 + hc + j * 4);
            v.x *= alpha; v.y *= alpha; v.z *= alpha; v.w *= alpha;
            if (Cf) *(float4*)(Cf + crow + j * 4) = v;
            if (Ch) {
                uint2 u = make_uint2(pack_f16(v.x, v.y), pack_f16(v.z, v.w));
                *(uint2*)(Ch + crow + j * 4) = u;
            }
        }
    }
}

// ---------------- fp32 SIMT NT GEMM (final projection, K=64) ----------------
__global__ __launch_bounds__(256) void gemm_f32nt(
    const float* __restrict__ A, const float* __restrict__ B, float* __restrict__ C,
    int M, int N, int K)
{
    constexpr int BM = 128, BN = 128, BK = 16;
    __shared__ float As[BK][BM];
    __shared__ float Bs[BK][BN];

    const int tid = threadIdx.x;
    const int tx  = tid & 15;
    const int ty  = tid >> 4;
    const int row0 = blockIdx.y * BM;
    const int col0 = blockIdx.x * BN;
    A += (size_t)row0 * K;
    B += (size_t)col0 * K;

    float acc[8][8];
#pragma unroll
    for (int i = 0; i < 8; i++)
#pragma unroll
        for (int j = 0; j < 8; j++) acc[i][j] = 0.f;

    const int lrow = tid >> 2;
    const int lcol = (tid & 3) << 2;

    for (int k0 = 0; k0 < K; k0 += BK) {
#pragma unroll
        for (int r = 0; r < 2; r++) {
            float4 va = *(const float4*)(A + (size_t)(lrow + r * 64) * K + (k0 + lcol));
            As[lcol + 0][lrow + r * 64] = va.x;
            As[lcol + 1][lrow + r * 64] = va.y;
            As[lcol + 2][lrow + r * 64] = va.z;
            As[lcol + 3][lrow + r * 64] = va.w;
            float4 vb = *(const float4*)(B + (size_t)(lrow + r * 64) * K + (k0 + lcol));
            Bs[lcol + 0][lrow + r * 64] = vb.x;
            Bs[lcol + 1][lrow + r * 64] = vb.y;
            Bs[lcol + 2][lrow + r * 64] = vb.z;
            Bs[lcol + 3][lrow + r * 64] = vb.w;
        }
        __syncthreads();
#pragma unroll
        for (int kk = 0; kk < BK; kk++) {
            float a[8], b[8];
            *(float4*)&a[0] = *(const float4*)&As[kk][ty * 8];
            *(float4*)&a[4] = *(const float4*)&As[kk][ty * 8 + 4];
            *(float4*)&b[0] = *(const float4*)&Bs[kk][tx * 8];
            *(float4*)&b[4] = *(const float4*)&Bs[kk][tx * 8 + 4];
#pragma unroll
            for (int i = 0; i < 8; i++)
#pragma unroll
                for (int j = 0; j < 8; j++)
                    acc[i][j] = fmaf(a[i], b[j], acc[i][j]);
        }
        __syncthreads();
    }
#pragma unroll
    for (int i = 0; i < 8; i++) {
        size_t crow = (size_t)(row0 + ty * 8 + i) * N + col0 + tx * 8;
#pragma unroll
        for (int j = 0; j < 8; j += 4)
            *(float4*)(C + crow + j) = make_float4(acc[i][j], acc[i][j + 1], acc[i][j + 2], acc[i][j + 3]);
    }
}

// ---------------- fp32 -> fp16 ----------------
__global__ __launch_bounds__(256) void conv_h(const float* __restrict__ src, __half* __restrict__ h)
{
    size_t i = ((size_t)blockIdx.x * 256 + threadIdx.x) * 4;
    float4 v = *(const float4*)(src + i);
    *(uint2*)(h + i) = make_uint2(pack_f16(v.x, v.y), pack_f16(v.z, v.w));
}

// ---------------- row softmax over 2048 cols -> fp16 ----------------
__global__ __launch_bounds__(256) void softmax_kernel(
    const float* __restrict__ S, __half* __restrict__ Wh)
{
    constexpr int C = T_, TPB = 256, PER = C / TPB;
    const float* row = S + (size_t)blockIdx.x * C;
    const int t = threadIdx.x;

    float v[PER];
    float m = -1e30f;
#pragma unroll
    for (int j = 0; j < PER; j++) { v[j] = row[t + j * TPB]; m = fmaxf(m, v[j]); }
    __shared__ float red[TPB];
    red[t] = m;
    __syncthreads();
#pragma unroll
    for (int s = TPB / 2; s > 0; s >>= 1) {
        if (t < s) red[t] = fmaxf(red[t], red[t + s]);
        __syncthreads();
    }
    m = red[0];
    __syncthreads();
    float sum = 0.f;
#pragma unroll
    for (int j = 0; j < PER; j++) { v[j] = expf(v[j] - m); sum += v[j]; }
    red[t] = sum;
    __syncthreads();
#pragma unroll
    for (int s = TPB / 2; s > 0; s >>= 1) {
        if (t < s) red[t] += red[t + s];
        __syncthreads();
    }
    float inv = 1.f / red[0];
    size_t base = (size_t)blockIdx.x * C;
#pragma unroll
    for (int j = 0; j < PER; j++)
        Wh[base + t + j * TPB] = __float2half(v[j] * inv);
}

// ---------------- quantum circuit ----------------
template <int BIT>
__device__ __forceinline__ void apply_ry_bit(float st[16], float half_theta)
{
    float s, c;
    sincosf(half_theta, &s, &c);
#pragma unroll
    for (int i = 0; i < 16; i++) {
        if (!(i & BIT)) {
            float a0 = st[i], a1 = st[i | BIT];
            st[i]       = c * a0 - s * a1;
            st[i | BIT] = s * a0 + c * a1;
        }
    }
}
template <int BC, int BT>
__device__ __forceinline__ void apply_cnot(float st[16])
{
#pragma unroll
    for (int i = 0; i < 16; i++) {
        if ((i & BC) && !(i & BT)) {
            float tmp = st[i]; st[i] = st[i | BT]; st[i | BT] = tmp;
        }
    }
}

__global__ void base_kernel(const float* __restrict__ qparams, float* __restrict__ base)
{
    int h = threadIdx.x;
    if (h >= H_) return;
    float st[16];
#pragma unroll
    for (int i = 0; i < 16; i++) st[i] = 0.f;
    st[0] = 1.f;
#pragma unroll
    for (int l = 0; l < LQ_; l++) {
        const float* p = qparams + (h * LQ_ + l) * 4;
        apply_ry_bit<8>(st, 0.5f * p[0]);
        apply_ry_bit<4>(st, 0.5f * p[1]);
        apply_ry_bit<2>(st, 0.5f * p[2]);
        apply_ry_bit<1>(st, 0.5f * p[3]);
        apply_cnot<8, 4>(st);
        apply_cnot<4, 2>(st);
        apply_cnot<2, 1>(st);
        apply_cnot<1, 8>(st);
    }
#pragma unroll
    for (int i = 0; i < 16; i++) base[h * 16 + i] = st[i];
}

__global__ __launch_bounds__(256) void quantum_kernel(
    const float* __restrict__ attn, const float* __restrict__ base, float* __restrict__ zc)
{
    int idx = blockIdx.x * 256 + threadIdx.x;
    if (idx >= NTOT_) return;
    int bt = idx >> 4;
    int h  = idx & 15;

    float st[16];
#pragma unroll
    for (int i = 0; i < 16; i++) st[i] = base[h * 16 + i];

    const float* xin = attn + (size_t)bt * E_ + h * 64;
    apply_ry_bit<8>(st, 0.5f * xin[0]);
    apply_ry_bit<4>(st, 0.5f * xin[1]);
    apply_ry_bit<2>(st, 0.5f * xin[2]);
    apply_ry_bit<1>(st, 0.5f * xin[3]);

    float z[4] = {0.f, 0.f, 0.f, 0.f};
#pragma unroll
    for (int i = 0; i < 16; i++) {
        float p = st[i] * st[i];
        z[0] += (i & 8) ? -p : p;
        z[1] += (i & 4) ? -p : p;
        z[2] += (i & 2) ? -p : p;
        z[3] += (i & 1) ? -p : p;
    }
    size_t o = (size_t)bt * 64 + h * 4;
    zc[o + 0] = z[0];
    zc[o + 1] = z[1];
    zc[o + 2] = z[2];
    zc[o + 3] = z[3];
}

// Gather the 64 useful columns of Wo (fp32)
__global__ void wosub_kernel(const float* __restrict__ Wo, float* __restrict__ ws)
{
    int idx = blockIdx.x * 256 + threadIdx.x;   // E_*64
    int e = idx >> 6, j = idx & 63;
    ws[idx] = Wo[(size_t)e * E_ + ((j >> 2) << 6) + (j & 3)];
}

// ---------------- launch ----------------
extern "C" void kernel_launch(void* const* d_in, const int* in_sizes, int n_in,
                              void* d_out, int out_size)
{
    (void)in_sizes; (void)n_in; (void)out_size;
    const float* x  = (const float*)d_in[0];
    const float* Wq = (const float*)d_in[1];
    const float* Wk = (const float*)d_in[2];
    const float* Wv = (const float*)d_in[3];
    const float* Wo = (const float*)d_in[4];
    const float* qp = (const float*)d_in[5];
    float* out = (float*)d_out;

    __half *xh, *wqh, *wkh, *wvh, *qh, *kh, *vth, *sh;
    float *ps, *pa, *pz, *pw, *pb;
    cudaGetSymbolAddress((void**)&xh,  g_xh);
    cudaGetSymbolAddress((void**)&wqh, g_wqh);
    cudaGetSymbolAddress((void**)&wkh, g_wkh);
    cudaGetSymbolAddress((void**)&wvh, g_wvh);
    cudaGetSymbolAddress((void**)&qh,  g_qh);
    cudaGetSymbolAddress((void**)&kh,  g_kh);
    cudaGetSymbolAddress((void**)&vth, g_vth);
    cudaGetSymbolAddress((void**)&sh,  g_sh);
    cudaGetSymbolAddress((void**)&ps,  g_s);
    cudaGetSymbolAddress((void**)&pa,  g_attn);
    cudaGetSymbolAddress((void**)&pz,  g_zc);
    cudaGetSymbolAddress((void**)&pw,  g_wosub);
    cudaGetSymbolAddress((void**)&pb,  g_base);

    cudaFuncSetAttribute(gemm_h, cudaFuncAttributeMaxDynamicSharedMemorySize, SMEM_DYN);

    conv_h<<<(M_ * E_) / 1024, 256>>>(x,  xh);
    conv_h<<<(E_ * E_) / 1024, 256>>>(Wq, wqh);
    conv_h<<<(E_ * E_) / 1024, 256>>>(Wk, wkh);
    conv_h<<<(E_ * E_) / 1024, 256>>>(Wv, wvh);
    base_kernel<<<1, 32>>>(qp, pb);
    wosub_kernel<<<(E_ * 64) / 256, 256>>>(Wo, pw);

    // Q = x Wq^T, K = x Wk^T (fp16 out)
    {
        dim3 g(E_ / 128, M_ / 128);
        gemm_h<<<g, 256, SMEM_DYN>>>(xh, wqh, nullptr, qh, E_, E_, E_, E_, 0, 0, 0, 1.f);
        gemm_h<<<g, 256, SMEM_DYN>>>(xh, wkh, nullptr, kh, E_, E_, E_, E_, 0, 0, 0, 1.f);
    }
    // V^T = Wv x^T : [E][M] fp16
    {
        dim3 g(M_ / 128, E_ / 128);
        gemm_h<<<g, 256, SMEM_DYN>>>(wvh, xh, nullptr, vth, E_, E_, E_, M_, 0, 0, 0, 1.f);
    }
    // scores = Q K^T / 32 (fp32 out), batched over B
    {
        dim3 g(T_ / 128, T_ / 128, B_);
        gemm_h<<<g, 256, SMEM_DYN>>>(qh, kh, ps, nullptr, E_, E_, E_, T_,
                                     (size_t)T_ * E_, (size_t)T_ * E_, (size_t)T_ * T_,
                                     1.f / 32.f);
    }
    softmax_kernel<<<M_, 256>>>(ps, sh);
    // attn = w @ V (fp32 out), batched
    {
        dim3 g(E_ / 128, T_ / 128, B_);
        gemm_h<<<g, 256, SMEM_DYN>>>(sh, vth, pa, nullptr, T_, T_, M_, E_,
                                     (size_t)T_ * T_, (size_t)T_, (size_t)T_ * E_,
                                     1.f);
    }
    quantum_kernel<<<NTOT_ / 256, 256>>>(pa, pb, pz);
    // out = zc @ WoSub^T (fp32 SIMT; unattenuated error path, keep exact)
    {
        dim3 g(E_ / 128, M_ / 128);
        gemm_f32nt<<<g, 256>>>(pz, pw, out, M_, E_, 64);
    }
}

// round 5
// speedup vs baseline: 7.3153x; 1.4206x over previous
#include <cuda_runtime.h>
#include <cuda_fp16.h>
#include <math.h>
#include <stdint.h>

// ---------------- problem constants ----------------
constexpr int B_  = 4;
constexpr int T_  = 2048;
constexpr int E_  = 1024;
constexpr int H_  = 16;
constexpr int LQ_ = 2;
constexpr int M_  = B_ * T_;        // 8192
constexpr int NTOT_ = M_ * H_;      // 131072

// ---------------- scratch (device globals; no allocs allowed) ----------------
__device__ __half g_xh[(size_t)M_ * E_];
__device__ __half g_wqh[(size_t)E_ * E_];
__device__ __half g_wkh[(size_t)E_ * E_];
__device__ __half g_wvsub[(size_t)64 * E_];        // gathered 64 rows of Wv (fp16)
__device__ __half g_qh[(size_t)M_ * E_];
__device__ __half g_kh[(size_t)M_ * E_];
__device__ __half g_vts[(size_t)64 * M_];          // Vtsub [64][M]
__device__ float  g_s[(size_t)B_ * T_ * T_];
__device__ __half g_sh[(size_t)B_ * T_ * T_];
__device__ float  g_attnT[(size_t)64 * M_];        // attn_sub^T [64][M]
__device__ float  g_zc[(size_t)M_ * 64];
__device__ float  g_wosub[(size_t)E_ * 64];
__device__ float  g_base[H_ * 16];

// ---------------- helpers ----------------
__device__ __forceinline__ uint32_t smem_u32(const void* p) {
    uint32_t a;
    asm("{ .reg .u64 t; cvta.to.shared.u64 t, %1; cvt.u32.u64 %0, t; }" : "=r"(a) : "l"(p));
    return a;
}
#define CP16(dst, src) asm volatile("cp.async.cg.shared.global [%0], [%1], 16;" :: "r"(dst), "l"(src))
#define CPCOMMIT()     asm volatile("cp.async.commit_group;")
#define CPWAIT2()      asm volatile("cp.async.wait_group 2;")

__device__ __forceinline__ void ldmx4(uint32_t* r, uint32_t addr) {
    asm volatile("ldmatrix.sync.aligned.m8n8.x4.shared.b16 {%0,%1,%2,%3}, [%4];"
                 : "=r"(r[0]), "=r"(r[1]), "=r"(r[2]), "=r"(r[3]) : "r"(addr));
}
__device__ __forceinline__ void mma16816(float* c, const uint32_t* a, const uint32_t* b) {
    asm volatile(
        "mma.sync.aligned.m16n8k16.row.col.f32.f16.f16.f32 "
        "{%0,%1,%2,%3}, {%4,%5,%6,%7}, {%8,%9}, {%0,%1,%2,%3};"
        : "+f"(c[0]), "+f"(c[1]), "+f"(c[2]), "+f"(c[3])
        : "r"(a[0]), "r"(a[1]), "r"(a[2]), "r"(a[3]), "r"(b[0]), "r"(b[1]));
}
__device__ __forceinline__ uint32_t pack_f16(float lo, float hi) {
    uint32_t u;
    asm("cvt.rn.f16x2.f32 %0, %1, %2;" : "=r"(u) : "f"(hi), "f"(lo));
    return u;
}

// ---------------- fp16 single-pass NT GEMM (mma.sync), BM x 128 tiles ----------------
// C[m,n] = alpha * sum_k A[m,k]*B[n,k]; fp32 accumulate. K%32==0.
constexpr int LDSB  = 80;                  // padded row: 32 halves (64B) + 16B pad

template <int BM>
__global__ __launch_bounds__(256, 2) void gemm_h(
    const __half* __restrict__ Ah, const __half* __restrict__ Bh,
    float* __restrict__ Cf, __half* __restrict__ Ch,
    int K, int lda, int ldb, int ldc,
    size_t sA, size_t sB, size_t sC, float alpha)
{
    constexpr int APLANE = BM * LDSB;
    constexpr int BPLANE = 128 * LDSB;
    constexpr int STAGE  = APLANE + BPLANE;
    constexpr int NSTG   = 4;
    constexpr int MF     = BM / 32;        // m-fragments per warp

    extern __shared__ char smem[];
    const uint32_t sb = smem_u32(smem);
    const int tid = threadIdx.x;
    const int lane = tid & 31;
    const int warp = tid >> 5;
    const int row0 = blockIdx.y * BM;
    const int col0 = blockIdx.x * 128;

    Ah += (size_t)blockIdx.z * sA;
    Bh += (size_t)blockIdx.z * sB;

    // A loader mapping
    const __half* gA;
    uint32_t aoff;
    if constexpr (BM == 128) {
        const int ar = tid >> 1, ac = (tid & 1) * 2;
        gA = Ah + (size_t)(row0 + ar) * lda + ac * 8;
        aoff = (uint32_t)(ar * LDSB + ac * 16);
    } else {
        const int ar = tid >> 2, ac = tid & 3;
        gA = Ah + (size_t)(row0 + ar) * lda + ac * 8;
        aoff = (uint32_t)(ar * LDSB + ac * 16);
    }
    // B loader mapping (128 rows, 2 chunks/thread)
    const int br = tid >> 1, bc = (tid & 1) * 2;
    const __half* gB = Bh + (size_t)(col0 + br) * ldb + bc * 8;
    const uint32_t boff = (uint32_t)(APLANE + br * LDSB + bc * 16);

    const int ntiles = K >> 5;

    auto load_tile = [&](int kt, int slot) {
        const uint32_t base = sb + (uint32_t)slot * STAGE;
        const __half* sa = gA + (size_t)kt * 32;
        const __half* sbp = gB + (size_t)kt * 32;
        if constexpr (BM == 128) {
            CP16(base + aoff,      sa);
            CP16(base + aoff + 16, sa + 8);
        } else {
            CP16(base + aoff, sa);
        }
        CP16(base + boff,      sbp);
        CP16(base + boff + 16, sbp + 8);
    };

    load_tile(0, 0); CPCOMMIT();
    load_tile(1, 1); CPCOMMIT();
    load_tile(2, 2); CPCOMMIT();

    const int wm = (warp & 1) * (BM / 2);
    const int wn = (warp >> 1) * 32;

    float acc[MF][4][4];
#pragma unroll
    for (int i = 0; i < MF; i++)
#pragma unroll
        for (int j = 0; j < 4; j++)
#pragma unroll
            for (int r = 0; r < 4; r++) acc[i][j][r] = 0.f;

    const uint32_t a_off = (uint32_t)((wm + (lane & 15)) * LDSB + ((lane >> 4) * 8) * 2);
    const int nrow = (lane & 7) + ((lane >> 4) * 8);
    const uint32_t b_off = (uint32_t)(APLANE + (wn + nrow) * LDSB + (((lane >> 3) & 1) * 8) * 2);

    for (int i = 0; i < ntiles; i++) {
        CPWAIT2();
        __syncthreads();
        if (i + 3 < ntiles) load_tile(i + 3, (i + 3) % NSTG);
        CPCOMMIT();

        const uint32_t st = sb + (uint32_t)(i % NSTG) * STAGE;
#pragma unroll
        for (int kk = 0; kk < 2; kk++) {
            uint32_t ah[MF][4], bh[4][2];
#pragma unroll
            for (int im = 0; im < MF; im++)
                ldmx4(ah[im], st + a_off + (uint32_t)(im * 16 * LDSB + kk * 32));
#pragma unroll
            for (int jb = 0; jb < 2; jb++) {
                uint32_t r[4];
                ldmx4(r, st + b_off + (uint32_t)(jb * 16 * LDSB + kk * 32));
                bh[jb * 2][0] = r[0];     bh[jb * 2][1] = r[1];
                bh[jb * 2 + 1][0] = r[2]; bh[jb * 2 + 1][1] = r[3];
            }
#pragma unroll
            for (int im = 0; im < MF; im++)
#pragma unroll
                for (int jn = 0; jn < 4; jn++)
                    mma16816(acc[im][jn], ah[im], bh[jn]);
        }
        __syncthreads();
    }

    // ---- epilogue: frags -> smem fp32 -> global ----
    float* se = (float*)smem;                        // [BM][132]
    const int er = wm + (lane >> 2);
    const int ec = wn + (lane & 3) * 2;
#pragma unroll
    for (int im = 0; im < MF; im++)
#pragma unroll
        for (int jn = 0; jn < 4; jn++) {
            float* p0 = se + (size_t)(er + im * 16) * 132 + ec + jn * 8;
            p0[0] = acc[im][jn][0];
            p0[1] = acc[im][jn][1];
            p0[132 * 8]     = acc[im][jn][2];
            p0[132 * 8 + 1] = acc[im][jn][3];
        }
    __syncthreads();
    {
        constexpr int TPR = 256 / BM;                // threads per row
        constexpr int CW  = 128 / TPR;               // cols per thread
        const int row = tid / TPR;
        const int hc  = (tid % TPR) * CW;
        const size_t crow = (size_t)blockIdx.z * sC + (size_t)(row0 + row) * ldc + col0 + hc;
#pragma unroll
        for (int j = 0; j < CW / 4; j++) {
            float4 v = *(const float4*)(se + (size_t)row * 132 + hc + j * 4);
            v.x *= alpha; v.y *= alpha; v.z *= alpha; v.w *= alpha;
            if (Cf) *(float4*)(Cf + crow + j * 4) = v;
            if (Ch) {
                uint2 u = make_uint2(pack_f16(v.x, v.y), pack_f16(v.z, v.w));
                *(uint2*)(Ch + crow + j * 4) = u;
            }
        }
    }
}

constexpr int SMEM_DYN_128 = 4 * (128 + 128) * LDSB;   // 81920
constexpr int SMEM_DYN_64  = 4 * (64 + 128) * LDSB;    // 61440

// ---------------- fp32 SIMT NT GEMM (final projection, K=64) ----------------
__global__ __launch_bounds__(256) void gemm_f32nt(
    const float* __restrict__ A, const float* __restrict__ B, float* __restrict__ C,
    int M, int N, int K)
{
    constexpr int BM = 128, BN = 128, BK = 16;
    __shared__ float As[BK][BM];
    __shared__ float Bs[BK][BN];

    const int tid = threadIdx.x;
    const int tx  = tid & 15;
    const int ty  = tid >> 4;
    const int row0 = blockIdx.y * BM;
    const int col0 = blockIdx.x * BN;
    A += (size_t)row0 * K;
    B += (size_t)col0 * K;

    float acc[8][8];
#pragma unroll
    for (int i = 0; i < 8; i++)
#pragma unroll
        for (int j = 0; j < 8; j++) acc[i][j] = 0.f;

    const int lrow = tid >> 2;
    const int lcol = (tid & 3) << 2;

    for (int k0 = 0; k0 < K; k0 += BK) {
#pragma unroll
        for (int r = 0; r < 2; r++) {
            float4 va = *(const float4*)(A + (size_t)(lrow + r * 64) * K + (k0 + lcol));
            As[lcol + 0][lrow + r * 64] = va.x;
            As[lcol + 1][lrow + r * 64] = va.y;
            As[lcol + 2][lrow + r * 64] = va.z;
            As[lcol + 3][lrow + r * 64] = va.w;
            float4 vb = *(const float4*)(B + (size_t)(lrow + r * 64) * K + (k0 + lcol));
            Bs[lcol + 0][lrow + r * 64] = vb.x;
            Bs[lcol + 1][lrow + r * 64] = vb.y;
            Bs[lcol + 2][lrow + r * 64] = vb.z;
            Bs[lcol + 3][lrow + r * 64] = vb.w;
        }
        __syncthreads();
#pragma unroll
        for (int kk = 0; kk < BK; kk++) {
            float a[8], b[8];
            *(float4*)&a[0] = *(const float4*)&As[kk][ty * 8];
            *(float4*)&a[4] = *(const float4*)&As[kk][ty * 8 + 4];
            *(float4*)&b[0] = *(const float4*)&Bs[kk][tx * 8];
            *(float4*)&b[4] = *(const float4*)&Bs[kk][tx * 8 + 4];
#pragma unroll
            for (int i = 0; i < 8; i++)
#pragma unroll
                for (int j = 0; j < 8; j++)
                    acc[i][j] = fmaf(a[i], b[j], acc[i][j]);
        }
        __syncthreads();
    }
#pragma unroll
    for (int i = 0; i < 8; i++) {
        size_t crow = (size_t)(row0 + ty * 8 + i) * N + col0 + tx * 8;
#pragma unroll
        for (int j = 0; j < 8; j += 4)
            *(float4*)(C + crow + j) = make_float4(acc[i][j], acc[i][j + 1], acc[i][j + 2], acc[i][j + 3]);
    }
}

// ---------------- fp32 -> fp16 ----------------
__global__ __launch_bounds__(256) void conv_h(const float* __restrict__ src, __half* __restrict__ h)
{
    size_t i = ((size_t)blockIdx.x * 256 + threadIdx.x) * 4;
    float4 v = *(const float4*)(src + i);
    *(uint2*)(h + i) = make_uint2(pack_f16(v.x, v.y), pack_f16(v.z, v.w));
}

// Gather 64 needed rows of Wv -> fp16: row j maps to Wv row (j>>2)*64 + (j&3)
__global__ __launch_bounds__(256) void wvsub_kernel(const float* __restrict__ Wv, __half* __restrict__ ws)
{
    int idx = blockIdx.x * 256 + threadIdx.x;       // 64*1024/4 = 16384 threads
    int j = idx >> 8;                               // 0..63
    int c = (idx & 255) * 4;
    const float* src = Wv + (size_t)((j >> 2) * 64 + (j & 3)) * E_ + c;
    float4 v = *(const float4*)src;
    *(uint2*)(ws + (size_t)j * E_ + c) = make_uint2(pack_f16(v.x, v.y), pack_f16(v.z, v.w));
}

// ---------------- row softmax over 2048 cols -> fp16 ----------------
__global__ __launch_bounds__(256) void softmax_kernel(
    const float* __restrict__ S, __half* __restrict__ Wh)
{
    constexpr int C = T_, TPB = 256, PER = C / TPB;
    const float* row = S + (size_t)blockIdx.x * C;
    const int t = threadIdx.x;

    float v[PER];
    float m = -1e30f;
#pragma unroll
    for (int j = 0; j < PER; j++) { v[j] = row[t + j * TPB]; m = fmaxf(m, v[j]); }
    __shared__ float red[TPB];
    red[t] = m;
    __syncthreads();
#pragma unroll
    for (int s = TPB / 2; s > 0; s >>= 1) {
        if (t < s) red[t] = fmaxf(red[t], red[t + s]);
        __syncthreads();
    }
    m = red[0];
    __syncthreads();
    float sum = 0.f;
#pragma unroll
    for (int j = 0; j < PER; j++) { v[j] = expf(v[j] - m); sum += v[j]; }
    red[t] = sum;
    __syncthreads();
#pragma unroll
    for (int s = TPB / 2; s > 0; s >>= 1) {
        if (t < s) red[t] += red[t + s];
        __syncthreads();
    }
    float inv = 1.f / red[0];
    size_t base = (size_t)blockIdx.x * C;
#pragma unroll
    for (int j = 0; j < PER; j++)
        Wh[base + t + j * TPB] = __float2half(v[j] * inv);
}

// ---------------- quantum circuit ----------------
template <int BIT>
__device__ __forceinline__ void apply_ry_bit(float st[16], float half_theta)
{
    float s, c;
    sincosf(half_theta, &s, &c);
#pragma unroll
    for (int i = 0; i < 16; i++) {
        if (!(i & BIT)) {
            float a0 = st[i], a1 = st[i | BIT];
            st[i]       = c * a0 - s * a1;
            st[i | BIT] = s * a0 + c * a1;
        }
    }
}
template <int BC, int BT>
__device__ __forceinline__ void apply_cnot(float st[16])
{
#pragma unroll
    for (int i = 0; i < 16; i++) {
        if ((i & BC) && !(i & BT)) {
            float tmp = st[i]; st[i] = st[i | BT]; st[i | BT] = tmp;
        }
    }
}

__global__ void base_kernel(const float* __restrict__ qparams, float* __restrict__ base)
{
    int h = threadIdx.x;
    if (h >= H_) return;
    float st[16];
#pragma unroll
    for (int i = 0; i < 16; i++) st[i] = 0.f;
    st[0] = 1.f;
#pragma unroll
    for (int l = 0; l < LQ_; l++) {
        const float* p = qparams + (h * LQ_ + l) * 4;
        apply_ry_bit<8>(st, 0.5f * p[0]);
        apply_ry_bit<4>(st, 0.5f * p[1]);
        apply_ry_bit<2>(st, 0.5f * p[2]);
        apply_ry_bit<1>(st, 0.5f * p[3]);
        apply_cnot<8, 4>(st);
        apply_cnot<4, 2>(st);
        apply_cnot<2, 1>(st);
        apply_cnot<1, 8>(st);
    }
#pragma unroll
    for (int i = 0; i < 16; i++) base[h * 16 + i] = st[i];
}

// idx = h*M_ + bt: coalesced reads from attnT [64][M]
__global__ __launch_bounds__(256) void quantum_kernel(
    const float* __restrict__ attnT, const float* __restrict__ base, float* __restrict__ zc)
{
    int idx = blockIdx.x * 256 + threadIdx.x;
    if (idx >= NTOT_) return;
    int h  = idx >> 13;          // /8192
    int bt = idx & (M_ - 1);

    float st[16];
#pragma unroll
    for (int i = 0; i < 16; i++) st[i] = base[h * 16 + i];

    apply_ry_bit<8>(st, 0.5f * attnT[(size_t)(h * 4 + 0) * M_ + bt]);
    apply_ry_bit<4>(st, 0.5f * attnT[(size_t)(h * 4 + 1) * M_ + bt]);
    apply_ry_bit<2>(st, 0.5f * attnT[(size_t)(h * 4 + 2) * M_ + bt]);
    apply_ry_bit<1>(st, 0.5f * attnT[(size_t)(h * 4 + 3) * M_ + bt]);

    float z[4] = {0.f, 0.f, 0.f, 0.f};
#pragma unroll
    for (int i = 0; i < 16; i++) {
        float p = st[i] * st[i];
        z[0] += (i & 8) ? -p : p;
        z[1] += (i & 4) ? -p : p;
        z[2] += (i & 2) ? -p : p;
        z[3] += (i & 1) ? -p : p;
    }
    size_t o = (size_t)bt * 64 + h * 4;
    zc[o + 0] = z[0];
    zc[o + 1] = z[1];
    zc[o + 2] = z[2];
    zc[o + 3] = z[3];
}

// Gather the 64 useful columns of Wo (fp32)
__global__ void wosub_kernel(const float* __restrict__ Wo, float* __restrict__ ws)
{
    int idx = blockIdx.x * 256 + threadIdx.x;   // E_*64
    int e = idx >> 6, j = idx & 63;
    ws[idx] = Wo[(size_t)e * E_ + ((j >> 2) << 6) + (j & 3)];
}

// ---------------- launch ----------------
extern "C" void kernel_launch(void* const* d_in, const int* in_sizes, int n_in,
                              void* d_out, int out_size)
{
    (void)in_sizes; (void)n_in; (void)out_size;
    const float* x  = (const float*)d_in[0];
    const float* Wq = (const float*)d_in[1];
    const float* Wk = (const float*)d_in[2];
    const float* Wv = (const float*)d_in[3];
    const float* Wo = (const float*)d_in[4];
    const float* qp = (const float*)d_in[5];
    float* out = (float*)d_out;

    __half *xh, *wqh, *wkh, *wvs, *qh, *kh, *vts, *sh;
    float *ps, *paT, *pz, *pw, *pb;
    cudaGetSymbolAddress((void**)&xh,  g_xh);
    cudaGetSymbolAddress((void**)&wqh, g_wqh);
    cudaGetSymbolAddress((void**)&wkh, g_wkh);
    cudaGetSymbolAddress((void**)&wvs, g_wvsub);
    cudaGetSymbolAddress((void**)&qh,  g_qh);
    cudaGetSymbolAddress((void**)&kh,  g_kh);
    cudaGetSymbolAddress((void**)&vts, g_vts);
    cudaGetSymbolAddress((void**)&sh,  g_sh);
    cudaGetSymbolAddress((void**)&ps,  g_s);
    cudaGetSymbolAddress((void**)&paT, g_attnT);
    cudaGetSymbolAddress((void**)&pz,  g_zc);
    cudaGetSymbolAddress((void**)&pw,  g_wosub);
    cudaGetSymbolAddress((void**)&pb,  g_base);

    cudaFuncSetAttribute(gemm_h<128>, cudaFuncAttributeMaxDynamicSharedMemorySize, SMEM_DYN_128);
    cudaFuncSetAttribute(gemm_h<64>,  cudaFuncAttributeMaxDynamicSharedMemorySize, SMEM_DYN_64);

    conv_h<<<(M_ * E_) / 1024, 256>>>(x,  xh);
    conv_h<<<(E_ * E_) / 1024, 256>>>(Wq, wqh);
    conv_h<<<(E_ * E_) / 1024, 256>>>(Wk, wkh);
    wvsub_kernel<<<(64 * E_) / 1024, 256>>>(Wv, wvs);
    base_kernel<<<1, 32>>>(qp, pb);
    wosub_kernel<<<(E_ * 64) / 256, 256>>>(Wo, pw);

    // Q = x Wq^T, K = x Wk^T (fp16 out)
    {
        dim3 g(E_ / 128, M_ / 128);
        gemm_h<128><<<g, 256, SMEM_DYN_128>>>(xh, wqh, nullptr, qh, E_, E_, E_, E_, 0, 0, 0, 1.f);
        gemm_h<128><<<g, 256, SMEM_DYN_128>>>(xh, wkh, nullptr, kh, E_, E_, E_, E_, 0, 0, 0, 1.f);
    }
    // Vtsub = Wvsub @ x^T : [64][M] fp16
    {
        dim3 g(M_ / 128, 1);
        gemm_h<64><<<g, 256, SMEM_DYN_64>>>(wvs, xh, nullptr, vts, E_, E_, E_, M_, 0, 0, 0, 1.f);
    }
    // scores = Q K^T / 32 (fp32 out), batched over B
    {
        dim3 g(T_ / 128, T_ / 128, B_);
        gemm_h<128><<<g, 256, SMEM_DYN_128>>>(qh, kh, ps, nullptr, E_, E_, E_, T_,
                                              (size_t)T_ * E_, (size_t)T_ * E_, (size_t)T_ * T_,
                                              1.f / 32.f);
    }
    softmax_kernel<<<M_, 256>>>(ps, sh);
    // attn_sub^T = Vtsub @ w^T : [64][T] per batch (fp32 out)
    // A[m,k] = Vtsub[m][b*T+k] (lda=M_, sA=T_); B = w rows (ldb=T_, sB=T*T); C cols at b*T (ldc=M_, sC=T_)
    {
        dim3 g(T_ / 128, 1, B_);
        gemm_h<64><<<g, 256, SMEM_DYN_64>>>(vts, sh, paT, nullptr, T_, M_, T_, M_,
                                            (size_t)T_, (size_t)T_ * T_, (size_t)T_,
                                            1.f);
    }
    quantum_kernel<<<NTOT_ / 256, 256>>>(paT, pb, pz);
    // out = zc @ WoSub^T (fp32 SIMT; unattenuated error path)
    {
        dim3 g(E_ / 128, M_ / 128);
        gemm_f32nt<<<g, 256>>>(pz, pw, out, M_, E_, 64);
    }
}

// round 6
// speedup vs baseline: 7.7092x; 1.0538x over previous
#include <cuda_runtime.h>
#include <cuda_fp16.h>
#include <math.h>
#include <stdint.h>

// ---------------- problem constants ----------------
constexpr int B_  = 4;
constexpr int T_  = 2048;
constexpr int E_  = 1024;
constexpr int H_  = 16;
constexpr int LQ_ = 2;
constexpr int M_  = B_ * T_;        // 8192
constexpr int NTOT_ = M_ * H_;      // 131072

// ---------------- scratch (device globals; no allocs allowed) ----------------
__device__ __half g_xh[(size_t)M_ * E_];
__device__ __half g_wqh[(size_t)E_ * E_];
__device__ __half g_wkh[(size_t)E_ * E_];
__device__ __half g_wvsub[(size_t)64 * E_];        // gathered 64 rows of Wv (fp16)
__device__ __half g_qh[(size_t)M_ * E_];
__device__ __half g_kh[(size_t)M_ * E_];
__device__ __half g_vts[(size_t)64 * M_];          // Vtsub [64][M]
__device__ __half g_sh[(size_t)B_ * T_ * T_];      // exp(scores-4) fp16
__device__ float  g_Z[(size_t)M_];                 // row sums of exp
__device__ float  g_attnT[(size_t)64 * M_];        // unnormalized attn_sub^T [64][M]
__device__ float  g_zc[(size_t)M_ * 64];
__device__ float  g_wosub[(size_t)E_ * 64];
__device__ float  g_base[H_ * 16];

// ---------------- helpers ----------------
__device__ __forceinline__ uint32_t smem_u32(const void* p) {
    uint32_t a;
    asm("{ .reg .u64 t; cvta.to.shared.u64 t, %1; cvt.u32.u64 %0, t; }" : "=r"(a) : "l"(p));
    return a;
}
#define CP16(dst, src) asm volatile("cp.async.cg.shared.global [%0], [%1], 16;" :: "r"(dst), "l"(src))
#define CPCOMMIT()     asm volatile("cp.async.commit_group;")
#define CPWAIT2()      asm volatile("cp.async.wait_group 2;")

__device__ __forceinline__ void ldmx4(uint32_t* r, uint32_t addr) {
    asm volatile("ldmatrix.sync.aligned.m8n8.x4.shared.b16 {%0,%1,%2,%3}, [%4];"
                 : "=r"(r[0]), "=r"(r[1]), "=r"(r[2]), "=r"(r[3]) : "r"(addr));
}
__device__ __forceinline__ void mma16816(float* c, const uint32_t* a, const uint32_t* b) {
    asm volatile(
        "mma.sync.aligned.m16n8k16.row.col.f32.f16.f16.f32 "
        "{%0,%1,%2,%3}, {%4,%5,%6,%7}, {%8,%9}, {%0,%1,%2,%3};"
        : "+f"(c[0]), "+f"(c[1]), "+f"(c[2]), "+f"(c[3])
        : "r"(a[0]), "r"(a[1]), "r"(a[2]), "r"(a[3]), "r"(b[0]), "r"(b[1]));
}
__device__ __forceinline__ uint32_t pack_f16(float lo, float hi) {
    uint32_t u;
    asm("cvt.rn.f16x2.f32 %0, %1, %2;" : "=r"(u) : "f"(hi), "f"(lo));
    return u;
}

// FMA-pipe exp(s - 4): magic-number range reduction + degree-5 2^f poly.
// Accurate to ~3e-6 rel on f in [-0.5, 0.5]; y clamped to avoid bit-trick overflow.
__device__ __forceinline__ float fexp4(float s) {
    float y = fmaf(s, 1.44269504f, -5.77078016f);      // (s-4)*log2(e)
    y = fminf(fmaxf(y, -30.f), 15.f);
    float t = y + 12582912.f;                           // 1.5*2^23 magic
    int   n = __float_as_int(t) - 0x4B400000;
    float f = y - (t - 12582912.f);
    float p =          1.3333558e-3f;
    p = fmaf(p, f, 9.6181291e-3f);
    p = fmaf(p, f, 5.5504109e-2f);
    p = fmaf(p, f, 2.4022651e-1f);
    p = fmaf(p, f, 6.9314718e-1f);
    p = fmaf(p, f, 1.0f);
    return __int_as_float(__float_as_int(p) + (n << 23));
}

// ---------------- fp16 single-pass NT GEMM (mma.sync), BM x 128 tiles ----------------
// C[m,n] = alpha * sum_k A[m,k]*B[n,k]; fp32 accumulate. K%32==0.
// EXPM: epilogue computes exp(alpha*acc - 4) and writes fp16 only.
constexpr int LDSB  = 80;                  // padded row: 32 halves (64B) + 16B pad

template <int BM, bool EXPM>
__global__ __launch_bounds__(256, 2) void gemm_h(
    const __half* __restrict__ Ah, const __half* __restrict__ Bh,
    float* __restrict__ Cf, __half* __restrict__ Ch,
    int K, int lda, int ldb, int ldc,
    size_t sA, size_t sB, size_t sC, float alpha)
{
    constexpr int APLANE = BM * LDSB;
    constexpr int BPLANE = 128 * LDSB;
    constexpr int STAGE  = APLANE + BPLANE;
    constexpr int NSTG   = 4;
    constexpr int MF     = BM / 32;        // m-fragments per warp

    extern __shared__ char smem[];
    const uint32_t sb = smem_u32(smem);
    const int tid = threadIdx.x;
    const int lane = tid & 31;
    const int warp = tid >> 5;
    const int row0 = blockIdx.y * BM;
    const int col0 = blockIdx.x * 128;

    Ah += (size_t)blockIdx.z * sA;
    Bh += (size_t)blockIdx.z * sB;

    // A loader mapping
    const __half* gA;
    uint32_t aoff;
    if constexpr (BM == 128) {
        const int ar = tid >> 1, ac = (tid & 1) * 2;
        gA = Ah + (size_t)(row0 + ar) * lda + ac * 8;
        aoff = (uint32_t)(ar * LDSB + ac * 16);
    } else {
        const int ar = tid >> 2, ac = tid & 3;
        gA = Ah + (size_t)(row0 + ar) * lda + ac * 8;
        aoff = (uint32_t)(ar * LDSB + ac * 16);
    }
    // B loader mapping (128 rows, 2 chunks/thread)
    const int br = tid >> 1, bc = (tid & 1) * 2;
    const __half* gB = Bh + (size_t)(col0 + br) * ldb + bc * 8;
    const uint32_t boff = (uint32_t)(APLANE + br * LDSB + bc * 16);

    const int ntiles = K >> 5;

    auto load_tile = [&](int kt, int slot) {
        const uint32_t base = sb + (uint32_t)slot * STAGE;
        const __half* sa = gA + (size_t)kt * 32;
        const __half* sbp = gB + (size_t)kt * 32;
        if constexpr (BM == 128) {
            CP16(base + aoff,      sa);
            CP16(base + aoff + 16, sa + 8);
        } else {
            CP16(base + aoff, sa);
        }
        CP16(base + boff,      sbp);
        CP16(base + boff + 16, sbp + 8);
    };

    load_tile(0, 0); CPCOMMIT();
    load_tile(1, 1); CPCOMMIT();
    load_tile(2, 2); CPCOMMIT();

    const int wm = (warp & 1) * (BM / 2);
    const int wn = (warp >> 1) * 32;

    float acc[MF][4][4];
#pragma unroll
    for (int i = 0; i < MF; i++)
#pragma unroll
        for (int j = 0; j < 4; j++)
#pragma unroll
            for (int r = 0; r < 4; r++) acc[i][j][r] = 0.f;

    const uint32_t a_off = (uint32_t)((wm + (lane & 15)) * LDSB + ((lane >> 4) * 8) * 2);
    const int nrow = (lane & 7) + ((lane >> 4) * 8);
    const uint32_t b_off = (uint32_t)(APLANE + (wn + nrow) * LDSB + (((lane >> 3) & 1) * 8) * 2);

    for (int i = 0; i < ntiles; i++) {
        CPWAIT2();
        __syncthreads();
        if (i + 3 < ntiles) load_tile(i + 3, (i + 3) % NSTG);
        CPCOMMIT();

        const uint32_t st = sb + (uint32_t)(i % NSTG) * STAGE;
#pragma unroll
        for (int kk = 0; kk < 2; kk++) {
            uint32_t ah[MF][4], bh[4][2];
#pragma unroll
            for (int im = 0; im < MF; im++)
                ldmx4(ah[im], st + a_off + (uint32_t)(im * 16 * LDSB + kk * 32));
#pragma unroll
            for (int jb = 0; jb < 2; jb++) {
                uint32_t r[4];
                ldmx4(r, st + b_off + (uint32_t)(jb * 16 * LDSB + kk * 32));
                bh[jb * 2][0] = r[0];     bh[jb * 2][1] = r[1];
                bh[jb * 2 + 1][0] = r[2]; bh[jb * 2 + 1][1] = r[3];
            }
#pragma unroll
            for (int im = 0; im < MF; im++)
#pragma unroll
                for (int jn = 0; jn < 4; jn++)
                    mma16816(acc[im][jn], ah[im], bh[jn]);
        }
        __syncthreads();
    }

    // ---- epilogue: frags -> smem fp32 -> global ----
    float* se = (float*)smem;                        // [BM][132]
    const int er = wm + (lane >> 2);
    const int ec = wn + (lane & 3) * 2;
#pragma unroll
    for (int im = 0; im < MF; im++)
#pragma unroll
        for (int jn = 0; jn < 4; jn++) {
            float* p0 = se + (size_t)(er + im * 16) * 132 + ec + jn * 8;
            p0[0] = acc[im][jn][0];
            p0[1] = acc[im][jn][1];
            p0[132 * 8]     = acc[im][jn][2];
            p0[132 * 8 + 1] = acc[im][jn][3];
        }
    __syncthreads();
    {
        constexpr int TPR = 256 / BM;                // threads per row
        constexpr int CW  = 128 / TPR;               // cols per thread
        const int row = tid / TPR;
        const int hc  = (tid % TPR) * CW;
        const size_t crow = (size_t)blockIdx.z * sC + (size_t)(row0 + row) * ldc + col0 + hc;
#pragma unroll
        for (int j = 0; j < CW / 4; j++) {
            float4 v = *(const float4*)(se + (size_t)row * 132 + hc + j * 4);
            v.x *= alpha; v.y *= alpha; v.z *= alpha; v.w *= alpha;
            if constexpr (EXPM) {
                v.x = fexp4(v.x); v.y = fexp4(v.y);
                v.z = fexp4(v.z); v.w = fexp4(v.w);
                uint2 u = make_uint2(pack_f16(v.x, v.y), pack_f16(v.z, v.w));
                *(uint2*)(Ch + crow + j * 4) = u;
            } else {
                if (Cf) *(float4*)(Cf + crow + j * 4) = v;
                if (Ch) {
                    uint2 u = make_uint2(pack_f16(v.x, v.y), pack_f16(v.z, v.w));
                    *(uint2*)(Ch + crow + j * 4) = u;
                }
            }
        }
    }
}

constexpr int SMEM_DYN_128 = 4 * (128 + 128) * LDSB;   // 81920
constexpr int SMEM_DYN_64  = 4 * (64 + 128) * LDSB;    // 61440

// ---------------- fp32 SIMT NT GEMM (final projection, K=64) ----------------
__global__ __launch_bounds__(256) void gemm_f32nt(
    const float* __restrict__ A, const float* __restrict__ B, float* __restrict__ C,
    int M, int N, int K)
{
    constexpr int BM = 128, BN = 128, BK = 16;
    __shared__ float As[BK][BM];
    __shared__ float Bs[BK][BN];

    const int tid = threadIdx.x;
    const int tx  = tid & 15;
    const int ty  = tid >> 4;
    const int row0 = blockIdx.y * BM;
    const int col0 = blockIdx.x * BN;
    A += (size_t)row0 * K;
    B += (size_t)col0 * K;

    float acc[8][8];
#pragma unroll
    for (int i = 0; i < 8; i++)
#pragma unroll
        for (int j = 0; j < 8; j++) acc[i][j] = 0.f;

    const int lrow = tid >> 2;
    const int lcol = (tid & 3) << 2;

    for (int k0 = 0; k0 < K; k0 += BK) {
#pragma unroll
        for (int r = 0; r < 2; r++) {
            float4 va = *(const float4*)(A + (size_t)(lrow + r * 64) * K + (k0 + lcol));
            As[lcol + 0][lrow + r * 64] = va.x;
            As[lcol + 1][lrow + r * 64] = va.y;
            As[lcol + 2][lrow + r * 64] = va.z;
            As[lcol + 3][lrow + r * 64] = va.w;
            float4 vb = *(const float4*)(B + (size_t)(lrow + r * 64) * K + (k0 + lcol));
            Bs[lcol + 0][lrow + r * 64] = vb.x;
            Bs[lcol + 1][lrow + r * 64] = vb.y;
            Bs[lcol + 2][lrow + r * 64] = vb.z;
            Bs[lcol + 3][lrow + r * 64] = vb.w;
        }
        __syncthreads();
#pragma unroll
        for (int kk = 0; kk < BK; kk++) {
            float a[8], b[8];
            *(float4*)&a[0] = *(const float4*)&As[kk][ty * 8];
            *(float4*)&a[4] = *(const float4*)&As[kk][ty * 8 + 4];
            *(float4*)&b[0] = *(const float4*)&Bs[kk][tx * 8];
            *(float4*)&b[4] = *(const float4*)&Bs[kk][tx * 8 + 4];
#pragma unroll
            for (int i = 0; i < 8; i++)
#pragma unroll
                for (int j = 0; j < 8; j++)
                    acc[i][j] = fmaf(a[i], b[j], acc[i][j]);
        }
        __syncthreads();
    }
#pragma unroll
    for (int i = 0; i < 8; i++) {
        size_t crow = (size_t)(row0 + ty * 8 + i) * N + col0 + tx * 8;
#pragma unroll
        for (int j = 0; j < 8; j += 4)
            *(float4*)(C + crow + j) = make_float4(acc[i][j], acc[i][j + 1], acc[i][j + 2], acc[i][j + 3]);
    }
}

// ---------------- fp32 -> fp16 ----------------
__global__ __launch_bounds__(256) void conv_h(const float* __restrict__ src, __half* __restrict__ h)
{
    size_t i = ((size_t)blockIdx.x * 256 + threadIdx.x) * 4;
    float4 v = *(const float4*)(src + i);
    *(uint2*)(h + i) = make_uint2(pack_f16(v.x, v.y), pack_f16(v.z, v.w));
}

// Gather 64 needed rows of Wv -> fp16: row j maps to Wv row (j>>2)*64 + (j&3)
__global__ __launch_bounds__(256) void wvsub_kernel(const float* __restrict__ Wv, __half* __restrict__ ws)
{
    int idx = blockIdx.x * 256 + threadIdx.x;
    int j = idx >> 8;
    int c = (idx & 255) * 4;
    const float* src = Wv + (size_t)((j >> 2) * 64 + (j & 3)) * E_ + c;
    float4 v = *(const float4*)src;
    *(uint2*)(ws + (size_t)j * E_ + c) = make_uint2(pack_f16(v.x, v.y), pack_f16(v.z, v.w));
}

// ---------------- row sums of exp matrix: Z[r] = sum_c expS[r][c] ----------------
__global__ __launch_bounds__(256) void rowsum_kernel(const __half* __restrict__ S, float* __restrict__ Z)
{
    const int row  = blockIdx.x * 8 + (threadIdx.x >> 5);
    const int lane = threadIdx.x & 31;
    const uint4* r = (const uint4*)(S + (size_t)row * T_);
    float s = 0.f;
#pragma unroll
    for (int j = 0; j < 8; j++) {
        uint4 u = r[lane + j * 32];
        float2 a = __half22float2(*(const __half2*)&u.x);
        float2 b = __half22float2(*(const __half2*)&u.y);
        float2 c = __half22float2(*(const __half2*)&u.z);
        float2 d = __half22float2(*(const __half2*)&u.w);
        s += (a.x + a.y) + (b.x + b.y) + (c.x + c.y) + (d.x + d.y);
    }
#pragma unroll
    for (int o = 16; o > 0; o >>= 1)
        s += __shfl_xor_sync(0xFFFFFFFFu, s, o);
    if (lane == 0) Z[row] = s;
}

// ---------------- quantum circuit ----------------
template <int BIT>
__device__ __forceinline__ void apply_ry_bit(float st[16], float half_theta)
{
    float s, c;
    sincosf(half_theta, &s, &c);
#pragma unroll
    for (int i = 0; i < 16; i++) {
        if (!(i & BIT)) {
            float a0 = st[i], a1 = st[i | BIT];
            st[i]       = c * a0 - s * a1;
            st[i | BIT] = s * a0 + c * a1;
        }
    }
}
template <int BC, int BT>
__device__ __forceinline__ void apply_cnot(float st[16])
{
#pragma unroll
    for (int i = 0; i < 16; i++) {
        if ((i & BC) && !(i & BT)) {
            float tmp = st[i]; st[i] = st[i | BT]; st[i | BT] = tmp;
        }
    }
}

__global__ void base_kernel(const float* __restrict__ qparams, float* __restrict__ base)
{
    int h = threadIdx.x;
    if (h >= H_) return;
    float st[16];
#pragma unroll
    for (int i = 0; i < 16; i++) st[i] = 0.f;
    st[0] = 1.f;
#pragma unroll
    for (int l = 0; l < LQ_; l++) {
        const float* p = qparams + (h * LQ_ + l) * 4;
        apply_ry_bit<8>(st, 0.5f * p[0]);
        apply_ry_bit<4>(st, 0.5f * p[1]);
        apply_ry_bit<2>(st, 0.5f * p[2]);
        apply_ry_bit<1>(st, 0.5f * p[3]);
        apply_cnot<8, 4>(st);
        apply_cnot<4, 2>(st);
        apply_cnot<2, 1>(st);
        apply_cnot<1, 8>(st);
    }
#pragma unroll
    for (int i = 0; i < 16; i++) base[h * 16 + i] = st[i];
}

// idx = h*M_ + bt; normalizes unnormalized attnT by Z[bt] on the fly.
__global__ __launch_bounds__(256) void quantum_kernel(
    const float* __restrict__ attnT, const float* __restrict__ Z,
    const float* __restrict__ base, float* __restrict__ zc)
{
    int idx = blockIdx.x * 256 + threadIdx.x;
    if (idx >= NTOT_) return;
    int h  = idx >> 13;
    int bt = idx & (M_ - 1);

    const float rz = 0.5f / Z[bt];

    float st[16];
#pragma unroll
    for (int i = 0; i < 16; i++) st[i] = base[h * 16 + i];

    apply_ry_bit<8>(st, rz * attnT[(size_t)(h * 4 + 0) * M_ + bt]);
    apply_ry_bit<4>(st, rz * attnT[(size_t)(h * 4 + 1) * M_ + bt]);
    apply_ry_bit<2>(st, rz * attnT[(size_t)(h * 4 + 2) * M_ + bt]);
    apply_ry_bit<1>(st, rz * attnT[(size_t)(h * 4 + 3) * M_ + bt]);

    float z[4] = {0.f, 0.f, 0.f, 0.f};
#pragma unroll
    for (int i = 0; i < 16; i++) {
        float p = st[i] * st[i];
        z[0] += (i & 8) ? -p : p;
        z[1] += (i & 4) ? -p : p;
        z[2] += (i & 2) ? -p : p;
        z[3] += (i & 1) ? -p : p;
    }
    size_t o = (size_t)bt * 64 + h * 4;
    zc[o + 0] = z[0];
    zc[o + 1] = z[1];
    zc[o + 2] = z[2];
    zc[o + 3] = z[3];
}

// Gather the 64 useful columns of Wo (fp32)
__global__ void wosub_kernel(const float* __restrict__ Wo, float* __restrict__ ws)
{
    int idx = blockIdx.x * 256 + threadIdx.x;
    int e = idx >> 6, j = idx & 63;
    ws[idx] = Wo[(size_t)e * E_ + ((j >> 2) << 6) + (j & 3)];
}

// ---------------- launch ----------------
extern "C" void kernel_launch(void* const* d_in, const int* in_sizes, int n_in,
                              void* d_out, int out_size)
{
    (void)in_sizes; (void)n_in; (void)out_size;
    const float* x  = (const float*)d_in[0];
    const float* Wq = (const float*)d_in[1];
    const float* Wk = (const float*)d_in[2];
    const float* Wv = (const float*)d_in[3];
    const float* Wo = (const float*)d_in[4];
    const float* qp = (const float*)d_in[5];
    float* out = (float*)d_out;

    __half *xh, *wqh, *wkh, *wvs, *qh, *kh, *vts, *sh;
    float *pZ, *paT, *pz, *pw, *pb;
    cudaGetSymbolAddress((void**)&xh,  g_xh);
    cudaGetSymbolAddress((void**)&wqh, g_wqh);
    cudaGetSymbolAddress((void**)&wkh, g_wkh);
    cudaGetSymbolAddress((void**)&wvs, g_wvsub);
    cudaGetSymbolAddress((void**)&qh,  g_qh);
    cudaGetSymbolAddress((void**)&kh,  g_kh);
    cudaGetSymbolAddress((void**)&vts, g_vts);
    cudaGetSymbolAddress((void**)&sh,  g_sh);
    cudaGetSymbolAddress((void**)&pZ,  g_Z);
    cudaGetSymbolAddress((void**)&paT, g_attnT);
    cudaGetSymbolAddress((void**)&pz,  g_zc);
    cudaGetSymbolAddress((void**)&pw,  g_wosub);
    cudaGetSymbolAddress((void**)&pb,  g_base);

    cudaFuncSetAttribute((const void*)gemm_h<128, false>, cudaFuncAttributeMaxDynamicSharedMemorySize, SMEM_DYN_128);
    cudaFuncSetAttribute((const void*)gemm_h<128, true>,  cudaFuncAttributeMaxDynamicSharedMemorySize, SMEM_DYN_128);
    cudaFuncSetAttribute((const void*)gemm_h<64, false>,  cudaFuncAttributeMaxDynamicSharedMemorySize, SMEM_DYN_64);

    conv_h<<<(M_ * E_) / 1024, 256>>>(x,  xh);
    conv_h<<<(E_ * E_) / 1024, 256>>>(Wq, wqh);
    conv_h<<<(E_ * E_) / 1024, 256>>>(Wk, wkh);
    wvsub_kernel<<<(64 * E_) / 1024, 256>>>(Wv, wvs);
    base_kernel<<<1, 32>>>(qp, pb);
    wosub_kernel<<<(E_ * 64) / 256, 256>>>(Wo, pw);

    // Q = x Wq^T, K = x Wk^T (fp16 out)
    {
        dim3 g(E_ / 128, M_ / 128);
        gemm_h<128, false><<<g, 256, SMEM_DYN_128>>>(xh, wqh, nullptr, qh, E_, E_, E_, E_, 0, 0, 0, 1.f);
        gemm_h<128, false><<<g, 256, SMEM_DYN_128>>>(xh, wkh, nullptr, kh, E_, E_, E_, E_, 0, 0, 0, 1.f);
    }
    // Vtsub = Wvsub @ x^T : [64][M] fp16
    {
        dim3 g(M_ / 128, 1);
        gemm_h<64, false><<<g, 256, SMEM_DYN_64>>>(wvs, xh, nullptr, vts, E_, E_, E_, M_, 0, 0, 0, 1.f);
    }
    // expS = exp(Q K^T / 32 - 4) (fp16 out, fused exp epilogue), batched over B
    {
        dim3 g(T_ / 128, T_ / 128, B_);
        gemm_h<128, true><<<g, 256, SMEM_DYN_128>>>(qh, kh, nullptr, sh, E_, E_, E_, T_,
                                                    (size_t)T_ * E_, (size_t)T_ * E_, (size_t)T_ * T_,
                                                    1.f / 32.f);
    }
    // Z = row sums of expS
    rowsum_kernel<<<M_ / 8, 256>>>(sh, pZ);
    // attn~^T = Vtsub @ expS^T : [64][T] per batch (fp32, unnormalized)
    {
        dim3 g(T_ / 128, 1, B_);
        gemm_h<64, false><<<g, 256, SMEM_DYN_64>>>(vts, sh, paT, nullptr, T_, M_, T_, M_,
                                                   (size_t)T_, (size_t)T_ * T_, (size_t)T_,
                                                   1.f);
    }
    quantum_kernel<<<NTOT_ / 256, 256>>>(paT, pZ, pb, pz);
    // out = zc @ WoSub^T (fp32 SIMT; unattenuated error path)
    {
        dim3 g(E_ / 128, M_ / 128);
        gemm_f32nt<<<g, 256>>>(pz, pw, out, M_, E_, 64);
    }
}

// round 8
// speedup vs baseline: 8.3602x; 1.0844x over previous
#include <cuda_runtime.h>
#include <cuda_fp16.h>
#include <math.h>
#include <stdint.h>

// ---------------- problem constants ----------------
constexpr int B_  = 4;
constexpr int T_  = 2048;
constexpr int E_  = 1024;
constexpr int H_  = 16;
constexpr int LQ_ = 2;
constexpr int M_  = B_ * T_;             // 8192
constexpr int NTOT_ = M_ * H_;           // 131072
constexpr size_t PART_ = (size_t)64 * M_;  // one split-K partial plane (fp32)

// ---------------- scratch (device globals; no allocs allowed) ----------------
__device__ __half g_xh[(size_t)M_ * E_];
__device__ __half g_wqk[(size_t)2 * E_ * E_];      // [Wq ; Wk] rows (fp16)
__device__ __half g_wvsub[(size_t)64 * E_];        // gathered 64 rows of Wv (fp16)
__device__ __half g_qk[(size_t)M_ * 2 * E_];       // [Q | K] (fp16, ld 2048)
__device__ __half g_vts[(size_t)64 * M_];          // Vtsub [64][M]
__device__ __half g_sh[(size_t)B_ * T_ * T_];      // exp(scores-4) fp16
__device__ float  g_Z[(size_t)M_];                 // row sums of exp
__device__ float  g_part[4 * PART_];               // split-K partials (reused)
__device__ __half g_zc192[(size_t)M_ * 192];       // [z_hi | z_lo | z_hi]
__device__ __half g_wo192[(size_t)E_ * 192];       // [W_hi | W_hi | W_lo]
__device__ float  g_base[H_ * 16];

// ---------------- helpers ----------------
__device__ __forceinline__ uint32_t smem_u32(const void* p) {
    uint32_t a;
    asm("{ .reg .u64 t; cvta.to.shared.u64 t, %1; cvt.u32.u64 %0, t; }" : "=r"(a) : "l"(p));
    return a;
}
#define CP16(dst, src) asm volatile("cp.async.cg.shared.global [%0], [%1], 16;" :: "r"(dst), "l"(src))
#define CPCOMMIT()     asm volatile("cp.async.commit_group;")
#define CPWAIT2()      asm volatile("cp.async.wait_group 2;")

__device__ __forceinline__ void ldmx4(uint32_t* r, uint32_t addr) {
    asm volatile("ldmatrix.sync.aligned.m8n8.x4.shared.b16 {%0,%1,%2,%3}, [%4];"
                 : "=r"(r[0]), "=r"(r[1]), "=r"(r[2]), "=r"(r[3]) : "r"(addr));
}
__device__ __forceinline__ void mma16816(float* c, const uint32_t* a, const uint32_t* b) {
    asm volatile(
        "mma.sync.aligned.m16n8k16.row.col.f32.f16.f16.f32 "
        "{%0,%1,%2,%3}, {%4,%5,%6,%7}, {%8,%9}, {%0,%1,%2,%3};"
        : "+f"(c[0]), "+f"(c[1]), "+f"(c[2]), "+f"(c[3])
        : "r"(a[0]), "r"(a[1]), "r"(a[2]), "r"(a[3]), "r"(b[0]), "r"(b[1]));
}
__device__ __forceinline__ uint32_t pack_f16(float lo, float hi) {
    uint32_t u;
    asm("cvt.rn.f16x2.f32 %0, %1, %2;" : "=r"(u) : "f"(hi), "f"(lo));
    return u;
}

// FMA-pipe exp(s - 4): magic-number range reduction + degree-5 2^f poly.
__device__ __forceinline__ float fexp4(float s) {
    float y = fmaf(s, 1.44269504f, -5.77078016f);      // (s-4)*log2(e)
    y = fminf(fmaxf(y, -30.f), 15.f);
    float t = y + 12582912.f;                           // 1.5*2^23 magic
    int   n = __float_as_int(t) - 0x4B400000;
    float f = y - (t - 12582912.f);
    float p =          1.3333558e-3f;
    p = fmaf(p, f, 9.6181291e-3f);
    p = fmaf(p, f, 5.5504109e-2f);
    p = fmaf(p, f, 2.4022651e-1f);
    p = fmaf(p, f, 6.9314718e-1f);
    p = fmaf(p, f, 1.0f);
    return __int_as_float(__float_as_int(p) + (n << 23));
}

// ---------------- fp16 single-pass NT GEMM (mma.sync), BM x 128 tiles ----------------
// C[m,n] = alpha * sum_k A[m,k]*B[n,k]; fp32 acc. K%(32*nsplit)==0.
// blockIdx.z = zb*nsplit + sp; split sp covers k in [sp*K/nsplit, (sp+1)*K/nsplit),
// writing to Cf + sp*partStride. EXPM: epilogue exp(alpha*acc-4) -> fp16.
constexpr int LDSB  = 80;

template <int BM, bool EXPM>
__global__ __launch_bounds__(256, 2) void gemm_h(
    const __half* __restrict__ Ah, const __half* __restrict__ Bh,
    float* __restrict__ Cf, __half* __restrict__ Ch,
    int K, int lda, int ldb, int ldc,
    size_t sA, size_t sB, size_t sC, float alpha,
    int nsplit, size_t partStride)
{
    constexpr int APLANE = BM * LDSB;
    constexpr int BPLANE = 128 * LDSB;
    constexpr int STAGE  = APLANE + BPLANE;
    constexpr int NSTG   = 4;
    constexpr int MF     = BM / 32;

    extern __shared__ char smem[];
    const uint32_t sb = smem_u32(smem);
    const int tid = threadIdx.x;
    const int lane = tid & 31;
    const int warp = tid >> 5;
    const int row0 = blockIdx.y * BM;
    const int col0 = blockIdx.x * 128;

    const int zb = blockIdx.z / nsplit;
    const int sp = blockIdx.z - zb * nsplit;
    const int Keff = K / nsplit;

    Ah += zb * sA + (size_t)sp * Keff;
    Bh += zb * sB + (size_t)sp * Keff;
    Cf += (size_t)sp * partStride;

    // A loader mapping
    const __half* gA;
    uint32_t aoff;
    if constexpr (BM == 128) {
        const int ar = tid >> 1, ac = (tid & 1) * 2;
        gA = Ah + (size_t)(row0 + ar) * lda + ac * 8;
        aoff = (uint32_t)(ar * LDSB + ac * 16);
    } else {
        const int ar = tid >> 2, ac = tid & 3;
        gA = Ah + (size_t)(row0 + ar) * lda + ac * 8;
        aoff = (uint32_t)(ar * LDSB + ac * 16);
    }
    // B loader mapping (128 rows, 2 chunks/thread)
    const int br = tid >> 1, bc = (tid & 1) * 2;
    const __half* gB = Bh + (size_t)(col0 + br) * ldb + bc * 8;
    const uint32_t boff = (uint32_t)(APLANE + br * LDSB + bc * 16);

    const int ntiles = Keff >> 5;

    auto load_tile = [&](int kt, int slot) {
        const uint32_t base = sb + (uint32_t)slot * STAGE;
        const __half* sa = gA + (size_t)kt * 32;
        const __half* sbp = gB + (size_t)kt * 32;
        if constexpr (BM == 128) {
            CP16(base + aoff,      sa);
            CP16(base + aoff + 16, sa + 8);
        } else {
            CP16(base + aoff, sa);
        }
        CP16(base + boff,      sbp);
        CP16(base + boff + 16, sbp + 8);
    };

    load_tile(0, 0); CPCOMMIT();
    load_tile(1, 1); CPCOMMIT();
    load_tile(2, 2); CPCOMMIT();

    const int wm = (warp & 1) * (BM / 2);
    const int wn = (warp >> 1) * 32;

    float acc[MF][4][4];
#pragma unroll
    for (int i = 0; i < MF; i++)
#pragma unroll
        for (int j = 0; j < 4; j++)
#pragma unroll
            for (int r = 0; r < 4; r++) acc[i][j][r] = 0.f;

    const uint32_t a_off = (uint32_t)((wm + (lane & 15)) * LDSB + ((lane >> 4) * 8) * 2);
    const int nrow = (lane & 7) + ((lane >> 4) * 8);
    const uint32_t b_off = (uint32_t)(APLANE + (wn + nrow) * LDSB + (((lane >> 3) & 1) * 8) * 2);

    for (int i = 0; i < ntiles; i++) {
        CPWAIT2();
        __syncthreads();
        if (i + 3 < ntiles) load_tile(i + 3, (i + 3) % NSTG);
        CPCOMMIT();

        const uint32_t st = sb + (uint32_t)(i % NSTG) * STAGE;
#pragma unroll
        for (int kk = 0; kk < 2; kk++) {
            uint32_t ah[MF][4], bh[4][2];
#pragma unroll
            for (int im = 0; im < MF; im++)
                ldmx4(ah[im], st + a_off + (uint32_t)(im * 16 * LDSB + kk * 32));
#pragma unroll
            for (int jb = 0; jb < 2; jb++) {
                uint32_t r[4];
                ldmx4(r, st + b_off + (uint32_t)(jb * 16 * LDSB + kk * 32));
                bh[jb * 2][0] = r[0];     bh[jb * 2][1] = r[1];
                bh[jb * 2 + 1][0] = r[2]; bh[jb * 2 + 1][1] = r[3];
            }
#pragma unroll
            for (int im = 0; im < MF; im++)
#pragma unroll
                for (int jn = 0; jn < 4; jn++)
                    mma16816(acc[im][jn], ah[im], bh[jn]);
        }
        __syncthreads();
    }

    // ---- epilogue: frags -> smem fp32 -> global ----
    float* se = (float*)smem;                        // [BM][132]
    const int er = wm + (lane >> 2);
    const int ec = wn + (lane & 3) * 2;
#pragma unroll
    for (int im = 0; im < MF; im++)
#pragma unroll
        for (int jn = 0; jn < 4; jn++) {
            float* p0 = se + (size_t)(er + im * 16) * 132 + ec + jn * 8;
            p0[0] = acc[im][jn][0];
            p0[1] = acc[im][jn][1];
            p0[132 * 8]     = acc[im][jn][2];
            p0[132 * 8 + 1] = acc[im][jn][3];
        }
    __syncthreads();
    {
        constexpr int TPR = 256 / BM;
        constexpr int CW  = 128 / TPR;
        const int row = tid / TPR;
        const int hc  = (tid % TPR) * CW;
        const size_t crow = (size_t)zb * sC + (size_t)(row0 + row) * ldc + col0 + hc;
#pragma unroll
        for (int j = 0; j < CW / 4; j++) {
            float4 v = *(const float4*)(se + (size_t)row * 132 + hc + j * 4);
            v.x *= alpha; v.y *= alpha; v.z *= alpha; v.w *= alpha;
            if constexpr (EXPM) {
                v.x = fexp4(v.x); v.y = fexp4(v.y);
                v.z = fexp4(v.z); v.w = fexp4(v.w);
                uint2 u = make_uint2(pack_f16(v.x, v.y), pack_f16(v.z, v.w));
                *(uint2*)(Ch + crow + j * 4) = u;
            } else {
                if (Cf) *(float4*)(Cf + crow + j * 4) = v;
                if (Ch) {
                    uint2 u = make_uint2(pack_f16(v.x, v.y), pack_f16(v.z, v.w));
                    *(uint2*)(Ch + crow + j * 4) = u;
                }
            }
        }
    }
}

constexpr int SMEM_DYN_128 = 4 * (128 + 128) * LDSB;   // 81920
constexpr int SMEM_DYN_64  = 4 * (64 + 128) * LDSB;    // 61440

// ---------------- fp32 -> fp16 ----------------
__global__ __launch_bounds__(256) void conv_h(const float* __restrict__ src, __half* __restrict__ h)
{
    size_t i = ((size_t)blockIdx.x * 256 + threadIdx.x) * 4;
    float4 v = *(const float4*)(src + i);
    *(uint2*)(h + i) = make_uint2(pack_f16(v.x, v.y), pack_f16(v.z, v.w));
}

// Gather 64 needed rows of Wv -> fp16: row j maps to Wv row (j>>2)*64 + (j&3)
__global__ __launch_bounds__(256) void wvsub_kernel(const float* __restrict__ Wv, __half* __restrict__ ws)
{
    int idx = blockIdx.x * 256 + threadIdx.x;
    int j = idx >> 8;
    int c = (idx & 255) * 4;
    const float* src = Wv + (size_t)((j >> 2) * 64 + (j & 3)) * E_ + c;
    float4 v = *(const float4*)src;
    *(uint2*)(ws + (size_t)j * E_ + c) = make_uint2(pack_f16(v.x, v.y), pack_f16(v.z, v.w));
}

// ---------------- reduce Vtsub split-K partials -> fp16 ----------------
__global__ __launch_bounds__(256) void vred_kernel(const float* __restrict__ p, __half* __restrict__ vts)
{
    size_t i = ((size_t)blockIdx.x * 256 + threadIdx.x) * 4;
    float4 a = *(const float4*)(p + i);
    float4 b = *(const float4*)(p + i + PART_);
    float4 c = *(const float4*)(p + i + 2 * PART_);
    float4 d = *(const float4*)(p + i + 3 * PART_);
    a.x += b.x + c.x + d.x;
    a.y += b.y + c.y + d.y;
    a.z += b.z + c.z + d.z;
    a.w += b.w + c.w + d.w;
    *(uint2*)(vts + i) = make_uint2(pack_f16(a.x, a.y), pack_f16(a.z, a.w));
}

// ---------------- row sums of exp matrix ----------------
__global__ __launch_bounds__(256) void rowsum_kernel(const __half* __restrict__ S, float* __restrict__ Z)
{
    const int row  = blockIdx.x * 8 + (threadIdx.x >> 5);
    const int lane = threadIdx.x & 31;
    const uint4* r = (const uint4*)(S + (size_t)row * T_);
    float s = 0.f;
#pragma unroll
    for (int j = 0; j < 8; j++) {
        uint4 u = r[lane + j * 32];
        float2 a = __half22float2(*(const __half2*)&u.x);
        float2 b = __half22float2(*(const __half2*)&u.y);
        float2 c = __half22float2(*(const __half2*)&u.z);
        float2 d = __half22float2(*(const __half2*)&u.w);
        s += (a.x + a.y) + (b.x + b.y) + (c.x + c.y) + (d.x + d.y);
    }
#pragma unroll
    for (int o = 16; o > 0; o >>= 1)
        s += __shfl_xor_sync(0xFFFFFFFFu, s, o);
    if (lane == 0) Z[row] = s;
}

// ---------------- quantum circuit ----------------
template <int BIT>
__device__ __forceinline__ void apply_ry_bit(float st[16], float half_theta)
{
    float s, c;
    sincosf(half_theta, &s, &c);
#pragma unroll
    for (int i = 0; i < 16; i++) {
        if (!(i & BIT)) {
            float a0 = st[i], a1 = st[i | BIT];
            st[i]       = c * a0 - s * a1;
            st[i | BIT] = s * a0 + c * a1;
        }
    }
}
template <int BC, int BT>
__device__ __forceinline__ void apply_cnot(float st[16])
{
#pragma unroll
    for (int i = 0; i < 16; i++) {
        if ((i & BC) && !(i & BT)) {
            float tmp = st[i]; st[i] = st[i | BT]; st[i | BT] = tmp;
        }
    }
}

__global__ void base_kernel(const float* __restrict__ qparams, float* __restrict__ base)
{
    int h = threadIdx.x;
    if (h >= H_) return;
    float st[16];
#pragma unroll
    for (int i = 0; i < 16; i++) st[i] = 0.f;
    st[0] = 1.f;
#pragma unroll
    for (int l = 0; l < LQ_; l++) {
        const float* p = qparams + (h * LQ_ + l) * 4;
        apply_ry_bit<8>(st, 0.5f * p[0]);
        apply_ry_bit<4>(st, 0.5f * p[1]);
        apply_ry_bit<2>(st, 0.5f * p[2]);
        apply_ry_bit<1>(st, 0.5f * p[3]);
        apply_cnot<8, 4>(st);
        apply_cnot<4, 2>(st);
        apply_cnot<2, 1>(st);
        apply_cnot<1, 8>(st);
    }
#pragma unroll
    for (int i = 0; i < 16; i++) base[h * 16 + i] = st[i];
}

// Sums 4 split-K partials of attnT, normalizes by Z, runs circuit,
// writes zc192 planes [z_hi | z_lo | z_hi].
__global__ __launch_bounds__(256) void quantum_kernel(
    const float* __restrict__ ap, const float* __restrict__ Z,
    const float* __restrict__ base, __half* __restrict__ zc192)
{
    int idx = blockIdx.x * 256 + threadIdx.x;
    if (idx >= NTOT_) return;
    int h  = idx >> 13;
    int bt = idx & (M_ - 1);

    const float rz = 0.5f / Z[bt];

    float ang[4];
#pragma unroll
    for (int q = 0; q < 4; q++) {
        size_t o = (size_t)(h * 4 + q) * M_ + bt;
        float s = ap[o] + ap[o + PART_] + ap[o + 2 * PART_] + ap[o + 3 * PART_];
        ang[q] = s * rz;
    }

    float st[16];
#pragma unroll
    for (int i = 0; i < 16; i++) st[i] = base[h * 16 + i];

    apply_ry_bit<8>(st, ang[0]);
    apply_ry_bit<4>(st, ang[1]);
    apply_ry_bit<2>(st, ang[2]);
    apply_ry_bit<1>(st, ang[3]);

    float z[4] = {0.f, 0.f, 0.f, 0.f};
#pragma unroll
    for (int i = 0; i < 16; i++) {
        float p = st[i] * st[i];
        z[0] += (i & 8) ? -p : p;
        z[1] += (i & 4) ? -p : p;
        z[2] += (i & 2) ? -p : p;
        z[3] += (i & 1) ? -p : p;
    }

    __half hq[4], lq[4];
#pragma unroll
    for (int q = 0; q < 4; q++) {
        hq[q] = __float2half(z[q]);
        lq[q] = __float2half(z[q] - __half2float(hq[q]));
    }
    __half2 h01 = __halves2half2(hq[0], hq[1]);
    __half2 h23 = __halves2half2(hq[2], hq[3]);
    __half2 l01 = __halves2half2(lq[0], lq[1]);
    __half2 l23 = __halves2half2(lq[2], lq[3]);

    size_t o = (size_t)bt * 192 + h * 4;
    *(__half2*)(zc192 + o)       = h01;
    *(__half2*)(zc192 + o + 2)   = h23;
    *(__half2*)(zc192 + o + 64)  = l01;
    *(__half2*)(zc192 + o + 66)  = l23;
    *(__half2*)(zc192 + o + 128) = h01;
    *(__half2*)(zc192 + o + 130) = h23;
}

// Gather 64 useful Wo columns into [W_hi | W_hi | W_lo] fp16 planes (K=192 rows)
__global__ void wosub_kernel(const float* __restrict__ Wo, __half* __restrict__ wo192)
{
    int idx = blockIdx.x * 256 + threadIdx.x;   // E_*64
    int e = idx >> 6, j = idx & 63;
    float v = Wo[(size_t)e * E_ + ((j >> 2) << 6) + (j & 3)];
    __half h = __float2half(v);
    __half l = __float2half(v - __half2float(h));
    size_t o = (size_t)e * 192 + j;
    wo192[o]       = h;
    wo192[o + 64]  = h;
    wo192[o + 128] = l;
}

// ---------------- launch ----------------
extern "C" void kernel_launch(void* const* d_in, const int* in_sizes, int n_in,
                              void* d_out, int out_size)
{
    (void)in_sizes; (void)n_in; (void)out_size;
    const float* x  = (const float*)d_in[0];
    const float* Wq = (const float*)d_in[1];
    const float* Wk = (const float*)d_in[2];
    const float* Wv = (const float*)d_in[3];
    const float* Wo = (const float*)d_in[4];
    const float* qp = (const float*)d_in[5];
    float* out = (float*)d_out;

    __half *xh, *wqk, *wvs, *qk, *vts, *sh, *zc192, *wo192;
    float *pZ, *part, *pb;
    cudaGetSymbolAddress((void**)&xh,    g_xh);
    cudaGetSymbolAddress((void**)&wqk,   g_wqk);
    cudaGetSymbolAddress((void**)&wvs,   g_wvsub);
    cudaGetSymbolAddress((void**)&qk,    g_qk);
    cudaGetSymbolAddress((void**)&vts,   g_vts);
    cudaGetSymbolAddress((void**)&sh,    g_sh);
    cudaGetSymbolAddress((void**)&pZ,    g_Z);
    cudaGetSymbolAddress((void**)&part,  g_part);
    cudaGetSymbolAddress((void**)&zc192, g_zc192);
    cudaGetSymbolAddress((void**)&wo192, g_wo192);
    cudaGetSymbolAddress((void**)&pb,    g_base);

    cudaFuncSetAttribute((const void*)gemm_h<128, false>, cudaFuncAttributeMaxDynamicSharedMemorySize, SMEM_DYN_128);
    cudaFuncSetAttribute((const void*)gemm_h<128, true>,  cudaFuncAttributeMaxDynamicSharedMemorySize, SMEM_DYN_128);
    cudaFuncSetAttribute((const void*)gemm_h<64, false>,  cudaFuncAttributeMaxDynamicSharedMemorySize, SMEM_DYN_64);

    conv_h<<<(M_ * E_) / 1024, 256>>>(x,  xh);
    conv_h<<<(E_ * E_) / 1024, 256>>>(Wq, wqk);
    conv_h<<<(E_ * E_) / 1024, 256>>>(Wk, wqk + (size_t)E_ * E_);
    wvsub_kernel<<<(64 * E_) / 1024, 256>>>(Wv, wvs);
    base_kernel<<<1, 32>>>(qp, pb);
    wosub_kernel<<<(E_ * 64) / 256, 256>>>(Wo, wo192);

    // [Q|K] = x @ [Wq;Wk]^T  (M=8192, N=2048, K=1024) -> fp16, ld 2048
    {
        dim3 g(2 * E_ / 128, M_ / 128);
        gemm_h<128, false><<<g, 256, SMEM_DYN_128>>>(xh, wqk, nullptr, qk,
                                                     E_, E_, E_, 2 * E_, 0, 0, 0, 1.f, 1, 0);
    }
    // Vtsub = Wvsub @ x^T : split-K 4 -> fp32 partials
    {
        dim3 g(M_ / 128, 1, 4);
        gemm_h<64, false><<<g, 256, SMEM_DYN_64>>>(wvs, xh, part, nullptr,
                                                   E_, E_, E_, M_, 0, 0, 0, 1.f, 4, PART_);
    }
    vred_kernel<<<(int)(PART_ / 1024), 256>>>(part, vts);
    // expS = exp(Q K^T / 32 - 4), fused epilogue, batched over B
    {
        dim3 g(T_ / 128, T_ / 128, B_);
        gemm_h<128, true><<<g, 256, SMEM_DYN_128>>>(qk, qk + E_, nullptr, sh,
                                                    E_, 2 * E_, 2 * E_, T_,
                                                    (size_t)T_ * 2 * E_, (size_t)T_ * 2 * E_, (size_t)T_ * T_,
                                                    1.f / 32.f, 1, 0);
    }
    rowsum_kernel<<<M_ / 8, 256>>>(sh, pZ);
    // attn~^T = Vtsub @ expS^T, split-K 4 per batch -> fp32 partials
    {
        dim3 g(T_ / 128, 1, B_ * 4);
        gemm_h<64, false><<<g, 256, SMEM_DYN_64>>>(vts, sh, part, nullptr,
                                                   T_, M_, T_, M_,
                                                   (size_t)T_, (size_t)T_ * T_, (size_t)T_,
                                                   1.f, 4, PART_);
    }
    quantum_kernel<<<NTOT_ / 256, 256>>>(part, pZ, pb, zc192);
    // out = zc @ WoSub^T via plane-concat K=192 fp16 GEMM (2-term hi/lo exact-enough)
    {
        dim3 g(E_ / 128, M_ / 128);
        gemm_h<128, false><<<g, 256, SMEM_DYN_128>>>(zc192, wo192, out, nullptr,
                                                     192, 192, 192, E_, 0, 0, 0, 1.f, 1, 0);
    }
}

// round 9
// speedup vs baseline: 9.7304x; 1.1639x over previous
#include <cuda_runtime.h>
#include <cuda_fp16.h>
#include <math.h>
#include <stdint.h>

// ---------------- problem constants ----------------
constexpr int B_  = 4;
constexpr int T_  = 2048;
constexpr int E_  = 1024;
constexpr int H_  = 16;
constexpr int LQ_ = 2;
constexpr int M_  = B_ * T_;             // 8192
constexpr int NTOT_ = M_ * H_;           // 131072
constexpr size_t PART_ = (size_t)64 * M_;  // one split-K partial plane (fp32)

// ---------------- scratch (device globals; no allocs allowed) ----------------
__device__ __half g_xh[(size_t)M_ * E_];
__device__ __half g_wqT[(size_t)E_ * E_];          // Wq^T (fp16)
__device__ __half g_wkT[(size_t)E_ * E_];          // Wk^T (fp16)
__device__ __half g_gt[(size_t)E_ * E_];           // G~^T = (Wq^T Wk / 32)^T (fp16)
__device__ __half g_yh[(size_t)M_ * E_];           // Y = x G~ (fp16)
__device__ __half g_wvsub[(size_t)64 * E_];        // gathered 64 rows of Wv (fp16)
__device__ __half g_vts[(size_t)64 * M_];          // Vtsub [64][M]
__device__ __half g_sh[(size_t)B_ * T_ * T_];      // exp(scores-4) fp16
__device__ float  g_Z[(size_t)M_];                 // row sums of exp
__device__ float  g_part[4 * PART_];               // split-K partials (reused)
__device__ __half g_zc192[(size_t)M_ * 192];       // [z_hi | z_lo | z_hi]
__device__ __half g_wo192[(size_t)E_ * 192];       // [W_hi | W_hi | W_lo]
__device__ float  g_base[H_ * 16];

// ---------------- helpers ----------------
__device__ __forceinline__ uint32_t smem_u32(const void* p) {
    uint32_t a;
    asm("{ .reg .u64 t; cvta.to.shared.u64 t, %1; cvt.u32.u64 %0, t; }" : "=r"(a) : "l"(p));
    return a;
}
#define CP16(dst, src) asm volatile("cp.async.cg.shared.global [%0], [%1], 16;" :: "r"(dst), "l"(src))
#define CPCOMMIT()     asm volatile("cp.async.commit_group;")
#define CPWAIT2()      asm volatile("cp.async.wait_group 2;")

__device__ __forceinline__ void ldmx4(uint32_t* r, uint32_t addr) {
    asm volatile("ldmatrix.sync.aligned.m8n8.x4.shared.b16 {%0,%1,%2,%3}, [%4];"
                 : "=r"(r[0]), "=r"(r[1]), "=r"(r[2]), "=r"(r[3]) : "r"(addr));
}
__device__ __forceinline__ void mma16816(float* c, const uint32_t* a, const uint32_t* b) {
    asm volatile(
        "mma.sync.aligned.m16n8k16.row.col.f32.f16.f16.f32 "
        "{%0,%1,%2,%3}, {%4,%5,%6,%7}, {%8,%9}, {%0,%1,%2,%3};"
        : "+f"(c[0]), "+f"(c[1]), "+f"(c[2]), "+f"(c[3])
        : "r"(a[0]), "r"(a[1]), "r"(a[2]), "r"(a[3]), "r"(b[0]), "r"(b[1]));
}
__device__ __forceinline__ uint32_t pack_f16(float lo, float hi) {
    uint32_t u;
    asm("cvt.rn.f16x2.f32 %0, %1, %2;" : "=r"(u) : "f"(hi), "f"(lo));
    return u;
}

// FMA-pipe exp(s - 4): magic-number range reduction + degree-5 2^f poly.
__device__ __forceinline__ float fexp4(float s) {
    float y = fmaf(s, 1.44269504f, -5.77078016f);      // (s-4)*log2(e)
    y = fminf(fmaxf(y, -30.f), 15.f);
    float t = y + 12582912.f;                           // 1.5*2^23 magic
    int   n = __float_as_int(t) - 0x4B400000;
    float f = y - (t - 12582912.f);
    float p =          1.3333558e-3f;
    p = fmaf(p, f, 9.6181291e-3f);
    p = fmaf(p, f, 5.5504109e-2f);
    p = fmaf(p, f, 2.4022651e-1f);
    p = fmaf(p, f, 6.9314718e-1f);
    p = fmaf(p, f, 1.0f);
    return __int_as_float(__float_as_int(p) + (n << 23));
}

// ---------------- fp16 single-pass NT GEMM (mma.sync), BM x 128 tiles ----------------
// C[m,n] = alpha * sum_k A[m,k]*B[n,k]; fp32 acc. K%(32*nsplit)==0.
// blockIdx.z = zb*nsplit + sp; split sp covers k-range sp, writes Cf + sp*partStride.
// EXPM: epilogue exp(alpha*acc-4) -> fp16 only.
constexpr int LDSB  = 80;

template <int BM, bool EXPM>
__global__ __launch_bounds__(256, 2) void gemm_h(
    const __half* __restrict__ Ah, const __half* __restrict__ Bh,
    float* __restrict__ Cf, __half* __restrict__ Ch,
    int K, int lda, int ldb, int ldc,
    size_t sA, size_t sB, size_t sC, float alpha,
    int nsplit, size_t partStride)
{
    constexpr int APLANE = BM * LDSB;
    constexpr int BPLANE = 128 * LDSB;
    constexpr int STAGE  = APLANE + BPLANE;
    constexpr int NSTG   = 4;
    constexpr int MF     = BM / 32;

    extern __shared__ char smem[];
    const uint32_t sb = smem_u32(smem);
    const int tid = threadIdx.x;
    const int lane = tid & 31;
    const int warp = tid >> 5;
    const int row0 = blockIdx.y * BM;
    const int col0 = blockIdx.x * 128;

    const int zb = blockIdx.z / nsplit;
    const int sp = blockIdx.z - zb * nsplit;
    const int Keff = K / nsplit;

    Ah += zb * sA + (size_t)sp * Keff;
    Bh += zb * sB + (size_t)sp * Keff;
    Cf += (size_t)sp * partStride;

    // A loader mapping
    const __half* gA;
    uint32_t aoff;
    if constexpr (BM == 128) {
        const int ar = tid >> 1, ac = (tid & 1) * 2;
        gA = Ah + (size_t)(row0 + ar) * lda + ac * 8;
        aoff = (uint32_t)(ar * LDSB + ac * 16);
    } else {
        const int ar = tid >> 2, ac = tid & 3;
        gA = Ah + (size_t)(row0 + ar) * lda + ac * 8;
        aoff = (uint32_t)(ar * LDSB + ac * 16);
    }
    // B loader mapping (128 rows, 2 chunks/thread)
    const int br = tid >> 1, bc = (tid & 1) * 2;
    const __half* gB = Bh + (size_t)(col0 + br) * ldb + bc * 8;
    const uint32_t boff = (uint32_t)(APLANE + br * LDSB + bc * 16);

    const int ntiles = Keff >> 5;

    auto load_tile = [&](int kt, int slot) {
        const uint32_t base = sb + (uint32_t)slot * STAGE;
        const __half* sa = gA + (size_t)kt * 32;
        const __half* sbp = gB + (size_t)kt * 32;
        if constexpr (BM == 128) {
            CP16(base + aoff,      sa);
            CP16(base + aoff + 16, sa + 8);
        } else {
            CP16(base + aoff, sa);
        }
        CP16(base + boff,      sbp);
        CP16(base + boff + 16, sbp + 8);
    };

    load_tile(0, 0); CPCOMMIT();
    load_tile(1, 1); CPCOMMIT();
    load_tile(2, 2); CPCOMMIT();

    const int wm = (warp & 1) * (BM / 2);
    const int wn = (warp >> 1) * 32;

    float acc[MF][4][4];
#pragma unroll
    for (int i = 0; i < MF; i++)
#pragma unroll
        for (int j = 0; j < 4; j++)
#pragma unroll
            for (int r = 0; r < 4; r++) acc[i][j][r] = 0.f;

    const uint32_t a_off = (uint32_t)((wm + (lane & 15)) * LDSB + ((lane >> 4) * 8) * 2);
    const int nrow = (lane & 7) + ((lane >> 4) * 8);
    const uint32_t b_off = (uint32_t)(APLANE + (wn + nrow) * LDSB + (((lane >> 3) & 1) * 8) * 2);

    for (int i = 0; i < ntiles; i++) {
        CPWAIT2();
        __syncthreads();
        if (i + 3 < ntiles) load_tile(i + 3, (i + 3) % NSTG);
        CPCOMMIT();

        const uint32_t st = sb + (uint32_t)(i % NSTG) * STAGE;
#pragma unroll
        for (int kk = 0; kk < 2; kk++) {
            uint32_t ah[MF][4], bh[4][2];
#pragma unroll
            for (int im = 0; im < MF; im++)
                ldmx4(ah[im], st + a_off + (uint32_t)(im * 16 * LDSB + kk * 32));
#pragma unroll
            for (int jb = 0; jb < 2; jb++) {
                uint32_t r[4];
                ldmx4(r, st + b_off + (uint32_t)(jb * 16 * LDSB + kk * 32));
                bh[jb * 2][0] = r[0];     bh[jb * 2][1] = r[1];
                bh[jb * 2 + 1][0] = r[2]; bh[jb * 2 + 1][1] = r[3];
            }
#pragma unroll
            for (int im = 0; im < MF; im++)
#pragma unroll
                for (int jn = 0; jn < 4; jn++)
                    mma16816(acc[im][jn], ah[im], bh[jn]);
        }
        __syncthreads();
    }

    // ---- epilogue: frags -> smem fp32 -> global ----
    float* se = (float*)smem;                        // [BM][132]
    const int er = wm + (lane >> 2);
    const int ec = wn + (lane & 3) * 2;
#pragma unroll
    for (int im = 0; im < MF; im++)
#pragma unroll
        for (int jn = 0; jn < 4; jn++) {
            float* p0 = se + (size_t)(er + im * 16) * 132 + ec + jn * 8;
            p0[0] = acc[im][jn][0];
            p0[1] = acc[im][jn][1];
            p0[132 * 8]     = acc[im][jn][2];
            p0[132 * 8 + 1] = acc[im][jn][3];
        }
    __syncthreads();
    {
        constexpr int TPR = 256 / BM;
        constexpr int CW  = 128 / TPR;
        const int row = tid / TPR;
        const int hc  = (tid % TPR) * CW;
        const size_t crow = (size_t)zb * sC + (size_t)(row0 + row) * ldc + col0 + hc;
#pragma unroll
        for (int j = 0; j < CW / 4; j++) {
            float4 v = *(const float4*)(se + (size_t)row * 132 + hc + j * 4);
            v.x *= alpha; v.y *= alpha; v.z *= alpha; v.w *= alpha;
            if constexpr (EXPM) {
                v.x = fexp4(v.x); v.y = fexp4(v.y);
                v.z = fexp4(v.z); v.w = fexp4(v.w);
                uint2 u = make_uint2(pack_f16(v.x, v.y), pack_f16(v.z, v.w));
                *(uint2*)(Ch + crow + j * 4) = u;
            } else {
                if (Cf) *(float4*)(Cf + crow + j * 4) = v;
                if (Ch) {
                    uint2 u = make_uint2(pack_f16(v.x, v.y), pack_f16(v.z, v.w));
                    *(uint2*)(Ch + crow + j * 4) = u;
                }
            }
        }
    }
}

constexpr int SMEM_DYN_128 = 4 * (128 + 128) * LDSB;   // 81920
constexpr int SMEM_DYN_64  = 4 * (64 + 128) * LDSB;    // 61440

// ---------------- quantum circuit device pieces ----------------
template <int BIT>
__device__ __forceinline__ void apply_ry_bit(float st[16], float half_theta)
{
    float s, c;
    sincosf(half_theta, &s, &c);
#pragma unroll
    for (int i = 0; i < 16; i++) {
        if (!(i & BIT)) {
            float a0 = st[i], a1 = st[i | BIT];
            st[i]       = c * a0 - s * a1;
            st[i | BIT] = s * a0 + c * a1;
        }
    }
}
template <int BC, int BT>
__device__ __forceinline__ void apply_cnot(float st[16])
{
#pragma unroll
    for (int i = 0; i < 16; i++) {
        if ((i & BC) && !(i & BT)) {
            float tmp = st[i]; st[i] = st[i | BT]; st[i | BT] = tmp;
        }
    }
}

// ---------------- fused prep: conv x, transpose Wq/Wk, wvsub, wosub, base ----------------
// grid partition: [0,8192) conv x | [8192,8448) T(Wq) | [8448,8704) T(Wk)
//                 [8704,8768) wvsub | [8768,9024) wosub | 9024 base
__global__ __launch_bounds__(256) void prep_kernel(
    const float* __restrict__ x,  const float* __restrict__ Wq,
    const float* __restrict__ Wk, const float* __restrict__ Wv,
    const float* __restrict__ Wo, const float* __restrict__ qp,
    __half* __restrict__ xh, __half* __restrict__ wqT, __half* __restrict__ wkT,
    __half* __restrict__ wvs, __half* __restrict__ wo192, float* __restrict__ base)
{
    __shared__ float ts[64][65];
    const int b = blockIdx.x;
    const int tid = threadIdx.x;

    if (b < 8192) {
        size_t i = ((size_t)b * 256 + tid) * 4;
        float4 v = *(const float4*)(x + i);
        *(uint2*)(xh + i) = make_uint2(pack_f16(v.x, v.y), pack_f16(v.z, v.w));
    } else if (b < 8704) {
        const bool isQ = b < 8448;
        const int tile = b - (isQ ? 8192 : 8448);
        const float* W = isQ ? Wq : Wk;
        __half* WT = isQ ? wqT : wkT;
        const int tr = (tile >> 4) * 64;    // source row base (e)
        const int tc = (tile & 15) * 64;    // source col base (i)
        const int lr = tid >> 2;
        const int lc = (tid & 3) * 16;
#pragma unroll
        for (int j = 0; j < 16; j += 4) {
            float4 v = *(const float4*)(W + (size_t)(tr + lr) * E_ + tc + lc + j);
            ts[lr][lc + j + 0] = v.x; ts[lr][lc + j + 1] = v.y;
            ts[lr][lc + j + 2] = v.z; ts[lr][lc + j + 3] = v.w;
        }
        __syncthreads();
#pragma unroll
        for (int j = 0; j < 16; j += 4) {
            uint2 u = make_uint2(
                pack_f16(ts[lc + j + 0][lr], ts[lc + j + 1][lr]),
                pack_f16(ts[lc + j + 2][lr], ts[lc + j + 3][lr]));
            *(uint2*)(WT + (size_t)(tc + lr) * E_ + tr + lc + j) = u;
        }
    } else if (b < 8768) {
        int idx = (b - 8704) * 256 + tid;
        int j = idx >> 8;
        int c = (idx & 255) * 4;
        const float* src = Wv + (size_t)((j >> 2) * 64 + (j & 3)) * E_ + c;
        float4 v = *(const float4*)src;
        *(uint2*)(wvs + (size_t)j * E_ + c) = make_uint2(pack_f16(v.x, v.y), pack_f16(v.z, v.w));
    } else if (b < 9024) {
        int idx = (b - 8768) * 256 + tid;
        int e = idx >> 6, j = idx & 63;
        float v = Wo[(size_t)e * E_ + ((j >> 2) << 6) + (j & 3)];
        __half h = __float2half(v);
        __half l = __float2half(v - __half2float(h));
        size_t o = (size_t)e * 192 + j;
        wo192[o]       = h;
        wo192[o + 64]  = h;
        wo192[o + 128] = l;
    } else if (tid < H_) {
        float st[16];
#pragma unroll
        for (int i = 0; i < 16; i++) st[i] = 0.f;
        st[0] = 1.f;
#pragma unroll
        for (int l = 0; l < LQ_; l++) {
            const float* p = qp + (tid * LQ_ + l) * 4;
            apply_ry_bit<8>(st, 0.5f * p[0]);
            apply_ry_bit<4>(st, 0.5f * p[1]);
            apply_ry_bit<2>(st, 0.5f * p[2]);
            apply_ry_bit<1>(st, 0.5f * p[3]);
            apply_cnot<8, 4>(st);
            apply_cnot<4, 2>(st);
            apply_cnot<2, 1>(st);
            apply_cnot<1, 8>(st);
        }
#pragma unroll
        for (int i = 0; i < 16; i++) base[tid * 16 + i] = st[i];
    }
}

// ---------------- reduce Vtsub split-K partials -> fp16 ----------------
__global__ __launch_bounds__(256) void vred_kernel(const float* __restrict__ p, __half* __restrict__ vts)
{
    size_t i = ((size_t)blockIdx.x * 256 + threadIdx.x) * 4;
    float4 a = *(const float4*)(p + i);
    float4 b = *(const float4*)(p + i + PART_);
    float4 c = *(const float4*)(p + i + 2 * PART_);
    float4 d = *(const float4*)(p + i + 3 * PART_);
    a.x += b.x + c.x + d.x;
    a.y += b.y + c.y + d.y;
    a.z += b.z + c.z + d.z;
    a.w += b.w + c.w + d.w;
    *(uint2*)(vts + i) = make_uint2(pack_f16(a.x, a.y), pack_f16(a.z, a.w));
}

// ---------------- row sums of exp matrix ----------------
__global__ __launch_bounds__(256) void rowsum_kernel(const __half* __restrict__ S, float* __restrict__ Z)
{
    const int row  = blockIdx.x * 8 + (threadIdx.x >> 5);
    const int lane = threadIdx.x & 31;
    const uint4* r = (const uint4*)(S + (size_t)row * T_);
    float s = 0.f;
#pragma unroll
    for (int j = 0; j < 8; j++) {
        uint4 u = r[lane + j * 32];
        float2 a = __half22float2(*(const __half2*)&u.x);
        float2 b = __half22float2(*(const __half2*)&u.y);
        float2 c = __half22float2(*(const __half2*)&u.z);
        float2 d = __half22float2(*(const __half2*)&u.w);
        s += (a.x + a.y) + (b.x + b.y) + (c.x + c.y) + (d.x + d.y);
    }
#pragma unroll
    for (int o = 16; o > 0; o >>= 1)
        s += __shfl_xor_sync(0xFFFFFFFFu, s, o);
    if (lane == 0) Z[row] = s;
}

// ---------------- quantum: sum partials, normalize, circuit, write zc192 planes ----------------
__global__ __launch_bounds__(256) void quantum_kernel(
    const float* __restrict__ ap, const float* __restrict__ Z,
    const float* __restrict__ base, __half* __restrict__ zc192)
{
    int idx = blockIdx.x * 256 + threadIdx.x;
    if (idx >= NTOT_) return;
    int h  = idx >> 13;
    int bt = idx & (M_ - 1);

    const float rz = 0.5f / Z[bt];

    float ang[4];
#pragma unroll
    for (int q = 0; q < 4; q++) {
        size_t o = (size_t)(h * 4 + q) * M_ + bt;
        float s = ap[o] + ap[o + PART_] + ap[o + 2 * PART_] + ap[o + 3 * PART_];
        ang[q] = s * rz;
    }

    float st[16];
#pragma unroll
    for (int i = 0; i < 16; i++) st[i] = base[h * 16 + i];

    apply_ry_bit<8>(st, ang[0]);
    apply_ry_bit<4>(st, ang[1]);
    apply_ry_bit<2>(st, ang[2]);
    apply_ry_bit<1>(st, ang[3]);

    float z[4] = {0.f, 0.f, 0.f, 0.f};
#pragma unroll
    for (int i = 0; i < 16; i++) {
        float p = st[i] * st[i];
        z[0] += (i & 8) ? -p : p;
        z[1] += (i & 4) ? -p : p;
        z[2] += (i & 2) ? -p : p;
        z[3] += (i & 1) ? -p : p;
    }

    __half hq[4], lq[4];
#pragma unroll
    for (int q = 0; q < 4; q++) {
        hq[q] = __float2half(z[q]);
        lq[q] = __float2half(z[q] - __half2float(hq[q]));
    }
    __half2 h01 = __halves2half2(hq[0], hq[1]);
    __half2 h23 = __halves2half2(hq[2], hq[3]);
    __half2 l01 = __halves2half2(lq[0], lq[1]);
    __half2 l23 = __halves2half2(lq[2], lq[3]);

    size_t o = (size_t)bt * 192 + h * 4;
    *(__half2*)(zc192 + o)       = h01;
    *(__half2*)(zc192 + o + 2)   = h23;
    *(__half2*)(zc192 + o + 64)  = l01;
    *(__half2*)(zc192 + o + 66)  = l23;
    *(__half2*)(zc192 + o + 128) = h01;
    *(__half2*)(zc192 + o + 130) = h23;
}

// ---------------- launch ----------------
extern "C" void kernel_launch(void* const* d_in, const int* in_sizes, int n_in,
                              void* d_out, int out_size)
{
    (void)in_sizes; (void)n_in; (void)out_size;
    const float* x  = (const float*)d_in[0];
    const float* Wq = (const float*)d_in[1];
    const float* Wk = (const float*)d_in[2];
    const float* Wv = (const float*)d_in[3];
    const float* Wo = (const float*)d_in[4];
    const float* qp = (const float*)d_in[5];
    float* out = (float*)d_out;

    __half *xh, *wqT, *wkT, *gt, *yh, *wvs, *vts, *sh, *zc192, *wo192;
    float *pZ, *part, *pb;
    cudaGetSymbolAddress((void**)&xh,    g_xh);
    cudaGetSymbolAddress((void**)&wqT,   g_wqT);
    cudaGetSymbolAddress((void**)&wkT,   g_wkT);
    cudaGetSymbolAddress((void**)&gt,    g_gt);
    cudaGetSymbolAddress((void**)&yh,    g_yh);
    cudaGetSymbolAddress((void**)&wvs,   g_wvsub);
    cudaGetSymbolAddress((void**)&vts,   g_vts);
    cudaGetSymbolAddress((void**)&sh,    g_sh);
    cudaGetSymbolAddress((void**)&pZ,    g_Z);
    cudaGetSymbolAddress((void**)&part,  g_part);
    cudaGetSymbolAddress((void**)&zc192, g_zc192);
    cudaGetSymbolAddress((void**)&wo192, g_wo192);
    cudaGetSymbolAddress((void**)&pb,    g_base);

    cudaFuncSetAttribute((const void*)gemm_h<128, false>, cudaFuncAttributeMaxDynamicSharedMemorySize, SMEM_DYN_128);
    cudaFuncSetAttribute((const void*)gemm_h<128, true>,  cudaFuncAttributeMaxDynamicSharedMemorySize, SMEM_DYN_128);
    cudaFuncSetAttribute((const void*)gemm_h<64, false>,  cudaFuncAttributeMaxDynamicSharedMemorySize, SMEM_DYN_64);

    // fused prep: conv x, transpose Wq/Wk to fp16, wvsub, wosub, base circuit
    prep_kernel<<<9025, 256>>>(x, Wq, Wk, Wv, Wo, qp, xh, wqT, wkT, wvs, wo192, pb);

    // Gt = (Wq^T Wk / 32)^T : Gt[m,n] = (1/32) sum_e WkT[m,e] WqT[n,e]  (fp16 out)
    {
        dim3 g(E_ / 128, E_ / 64);
        gemm_h<64, false><<<g, 256, SMEM_DYN_64>>>(wkT, wqT, nullptr, gt,
                                                   E_, E_, E_, E_, 0, 0, 0, 1.f / 32.f, 1, 0);
    }
    // Vtsub = Wvsub @ x^T : split-K 4 -> fp32 partials
    {
        dim3 g(M_ / 128, 1, 4);
        gemm_h<64, false><<<g, 256, SMEM_DYN_64>>>(wvs, xh, part, nullptr,
                                                   E_, E_, E_, M_, 0, 0, 0, 1.f, 4, PART_);
    }
    vred_kernel<<<(int)(PART_ / 1024), 256>>>(part, vts);
    // Y = x @ G~ : Y[m,n] = sum_k xh[m,k] Gt[n,k]  (fp16 out)
    {
        dim3 g(E_ / 128, M_ / 128);
        gemm_h<128, false><<<g, 256, SMEM_DYN_128>>>(xh, gt, nullptr, yh,
                                                     E_, E_, E_, E_, 0, 0, 0, 1.f, 1, 0);
    }
    // expS = exp(Y x^T - 4) (scores already scaled by 1/32 via G~), batched over B
    {
        dim3 g(T_ / 128, T_ / 128, B_);
        gemm_h<128, true><<<g, 256, SMEM_DYN_128>>>(yh, xh, nullptr, sh,
                                                    E_, E_, E_, T_,
                                                    (size_t)T_ * E_, (size_t)T_ * E_, (size_t)T_ * T_,
                                                    1.f, 1, 0);
    }
    rowsum_kernel<<<M_ / 8, 256>>>(sh, pZ);
    // attn~^T = Vtsub @ expS^T, split-K 4 per batch -> fp32 partials
    {
        dim3 g(T_ / 128, 1, B_ * 4);
        gemm_h<64, false><<<g, 256, SMEM_DYN_64>>>(vts, sh, part, nullptr,
                                                   T_, M_, T_, M_,
                                                   (size_t)T_, (size_t)T_ * T_, (size_t)T_,
                                                   1.f, 4, PART_);
    }
    quantum_kernel<<<NTOT_ / 256, 256>>>(part, pZ, pb, zc192);
    // out = zc @ WoSub^T via plane-concat K=192 fp16 GEMM
    {
        dim3 g(E_ / 128, M_ / 128);
        gemm_h<128, false><<<g, 256, SMEM_DYN_128>>>(zc192, wo192, out, nullptr,
                                                     192, 192, 192, E_, 0, 0, 0, 1.f, 1, 0);
    }
}